// round 1
// baseline (speedup 1.0000x reference)
#include <cuda_runtime.h>
#include <math.h>

#define N_NODES   50001
#define N_NBRS    12
#define N_GRAPHS  1000
#define NEG_BIG   (-9000000000000000.0f)
#define HD        256           // heads(8) * dim(32)

// Scratch ping-pong buffers (static device globals: allowed, no runtime alloc)
__device__ float g_buf0[(size_t)N_NODES * HD];
__device__ float g_buf1[(size_t)N_NODES * HD];

// ---------------------------------------------------------------------------
// GEMM: C[n, c] = sum_k A[n,k] * W[(c>>5)*K*32 + k*32 + (c&31)] + bias[c]
// Row 0 of C is overwritten with NEG_BIG (reference: h.at[:,0,:].set(NEG_BIG)).
// Block tile: 64 rows x 256 cols, 256 threads, 8x8 register micro-tile.
// ---------------------------------------------------------------------------
#define BM 64
#define BN 256
#define KC 16

__global__ __launch_bounds__(256, 2)
void gemm_kernel(const float* __restrict__ A, const float* __restrict__ W,
                 const float* __restrict__ bias, float* __restrict__ C, int K)
{
    __shared__ float Ast[KC][BM];      // transposed A tile
    __shared__ float Bs[KC][BN];

    const int tid  = threadIdx.x;
    const int tx   = tid & 31;         // 0..31  -> column group
    const int ty   = tid >> 5;         // 0..7   -> row group
    const int row0 = blockIdx.x * BM;

    float acc[8][8];
#pragma unroll
    for (int i = 0; i < 8; i++)
#pragma unroll
        for (int j = 0; j < 8; j++) acc[i][j] = 0.0f;

    for (int k0 = 0; k0 < K; k0 += KC) {
        // --- load A tile (64 x 16), transposed into Ast[kk][r] ---
        {
            int r = tid >> 2;          // 0..63
            int p = tid & 3;           // 0..3 -> 4 floats
            int gr = row0 + r;
            float4 v = make_float4(0.f, 0.f, 0.f, 0.f);
            if (gr < N_NODES)
                v = *(const float4*)(A + (size_t)gr * K + k0 + p * 4);
            Ast[p * 4 + 0][r] = v.x;
            Ast[p * 4 + 1][r] = v.y;
            Ast[p * 4 + 2][r] = v.z;
            Ast[p * 4 + 3][r] = v.w;
        }
        // --- load B tile (16 x 256): B[k][c] = W[((c>>5)*K + k)*32 + (c&31)] ---
        {
            int kk = tid >> 4;               // 0..15
            int cbase = (tid & 15) * 16;     // 0,16,...,240
            int k = k0 + kk;
#pragma unroll
            for (int q = 0; q < 4; q++) {
                int c = cbase + q * 4;
                int h = c >> 5, o = c & 31;
                float4 v = *(const float4*)(W + ((size_t)h * K + k) * 32 + o);
                *(float4*)&Bs[kk][c] = v;
            }
        }
        __syncthreads();

#pragma unroll
        for (int kk = 0; kk < KC; kk++) {
            float4 a0 = *(const float4*)&Ast[kk][ty * 8];
            float4 a1 = *(const float4*)&Ast[kk][ty * 8 + 4];
            float4 b0 = *(const float4*)&Bs[kk][tx * 4];
            float4 b1 = *(const float4*)&Bs[kk][128 + tx * 4];
            float a[8] = {a0.x, a0.y, a0.z, a0.w, a1.x, a1.y, a1.z, a1.w};
            float b[8] = {b0.x, b0.y, b0.z, b0.w, b1.x, b1.y, b1.z, b1.w};
#pragma unroll
            for (int i = 0; i < 8; i++)
#pragma unroll
                for (int j = 0; j < 8; j++)
                    acc[i][j] = fmaf(a[i], b[j], acc[i][j]);
        }
        __syncthreads();
    }

    // --- epilogue: bias add, row0 -> NEG_BIG, vectorized stores ---
#pragma unroll
    for (int i = 0; i < 8; i++) {
        int r = row0 + ty * 8 + i;
        if (r >= N_NODES) continue;
        float* crow = C + (size_t)r * HD;
#pragma unroll
        for (int half = 0; half < 2; half++) {
            int c = half * 128 + tx * 4;
            float4 v;
            v.x = acc[i][half * 4 + 0] + bias[c + 0];
            v.y = acc[i][half * 4 + 1] + bias[c + 1];
            v.z = acc[i][half * 4 + 2] + bias[c + 2];
            v.w = acc[i][half * 4 + 3] + bias[c + 3];
            if (r == 0) v = make_float4(NEG_BIG, NEG_BIG, NEG_BIG, NEG_BIG);
            *(float4*)(crow + c) = v;
        }
    }
}

// ---------------------------------------------------------------------------
// Attention: one warp per node. Lane layout: head = lane>>2, part = lane&3,
// each lane owns 8 consecutive floats of one head (32B -> coalesced 1KB/row).
// Online softmax over [self_score, 12 neighbor dots]; only attn[...,0] used.
// Row 0 output -> 0.
// ---------------------------------------------------------------------------
__global__ __launch_bounds__(256)
void attn_kernel(const float* __restrict__ H, const int* __restrict__ a2a32,
                 float* __restrict__ out)
{
    const int gwarp = (blockIdx.x * blockDim.x + threadIdx.x) >> 5;
    if (gwarp >= N_NODES) return;
    const int node = gwarp;
    const int lane = threadIdx.x & 31;
    const int head = lane >> 2;
    const int part = lane & 3;

    // int64-vs-int32 detection: values < 50001, so int64 high words are 0.
    const bool idx64 = ((a2a32[1] | a2a32[3] | a2a32[5] | a2a32[7]) == 0);

    const int off = head * 32 + part * 8;
    const float* hrow = H + (size_t)node * HD + off;
    float4 u0 = *(const float4*)hrow;
    float4 u1 = *(const float4*)(hrow + 4);
    float hn[8] = {u0.x, u0.y, u0.z, u0.w, u1.x, u1.y, u1.z, u1.w};

    // self score = ||h||^2 over this head's 32 dims (4-lane reduce)
    float s = 0.f;
#pragma unroll
    for (int i = 0; i < 8; i++) s = fmaf(hn[i], hn[i], s);
    s += __shfl_xor_sync(0xffffffffu, s, 1);
    s += __shfl_xor_sync(0xffffffffu, s, 2);

    const float s0 = s;
    float m = s, ssum = 1.0f;

#pragma unroll
    for (int k = 0; k < N_NBRS; k++) {
        int li = node * N_NBRS + k;
        int idx = idx64 ? a2a32[2 * li] : a2a32[li];
        const float* nrow = H + (size_t)idx * HD + off;
        float4 v0 = *(const float4*)nrow;
        float4 v1 = *(const float4*)(nrow + 4);
        float d = hn[0] * v0.x;
        d = fmaf(hn[1], v0.y, d);
        d = fmaf(hn[2], v0.z, d);
        d = fmaf(hn[3], v0.w, d);
        d = fmaf(hn[4], v1.x, d);
        d = fmaf(hn[5], v1.y, d);
        d = fmaf(hn[6], v1.z, d);
        d = fmaf(hn[7], v1.w, d);
        d += __shfl_xor_sync(0xffffffffu, d, 1);
        d += __shfl_xor_sync(0xffffffffu, d, 2);
        float nm = fmaxf(m, d);
        ssum = ssum * expf(m - nm) + expf(d - nm);
        m = nm;
    }

    float attn0 = expf(s0 - m) / ssum;
    if (node == 0) attn0 = 0.0f;

    float* orow = out + (size_t)node * HD + off;
    float4 o0 = make_float4(hn[0] * attn0, hn[1] * attn0, hn[2] * attn0, hn[3] * attn0);
    float4 o1 = make_float4(hn[4] * attn0, hn[5] * attn0, hn[6] * attn0, hn[7] * attn0);
    *(float4*)orow = o0;
    *(float4*)(orow + 4) = o1;
}

// ---------------------------------------------------------------------------
// Readout: graph_repr[g] = sum of node_repr rows (1+50g .. 50+50g)
// (segment_ids = [1000, 0 x50, 1 x50, ...] per the problem definition;
//  node 0's segment (1000) is dropped), then y = relu(g@Wo1+bo1)@Wo2+bo2.
// ---------------------------------------------------------------------------
__global__ __launch_bounds__(256)
void readout_kernel(const float* __restrict__ node_repr,
                    const float* __restrict__ Wo1, const float* __restrict__ bo1,
                    const float* __restrict__ Wo2, const float* __restrict__ bo2,
                    float* __restrict__ graph_repr, float* __restrict__ y)
{
    __shared__ float g[HD];
    const int gi = blockIdx.x;
    const int c  = threadIdx.x;

    float ssum = 0.f;
    const float* base = node_repr + (size_t)(1 + gi * 50) * HD + c;
#pragma unroll 10
    for (int r = 0; r < 50; r++) ssum += base[(size_t)r * HD];
    g[c] = ssum;
    graph_repr[(size_t)gi * HD + c] = ssum;
    __syncthreads();

    if (c < 32) {
        float acc = bo1[c];
#pragma unroll 8
        for (int d = 0; d < HD; d++) acc = fmaf(g[d], Wo1[d * 32 + c], acc);
        acc = fmaxf(acc, 0.0f);
        float val = acc * Wo2[c];
#pragma unroll
        for (int o = 16; o > 0; o >>= 1)
            val += __shfl_xor_sync(0xffffffffu, val, o);
        if (c == 0) y[gi] = val + bo2[0];
    }
}

// ---------------------------------------------------------------------------
extern "C" void kernel_launch(void* const* d_in, const int* in_sizes, int n_in,
                              void* d_out, int out_size)
{
    const float* x   = (const float*)d_in[0];
    const int*   a2a = (const int*)d_in[1];
    // d_in[2] = segment_ids (structure known from problem definition; unused)
    const float* W0  = (const float*)d_in[3];
    const float* b0  = (const float*)d_in[4];
    const float* W1  = (const float*)d_in[5];
    const float* b1  = (const float*)d_in[6];
    const float* W2  = (const float*)d_in[7];
    const float* b2  = (const float*)d_in[8];
    const float* Wo1 = (const float*)d_in[9];
    const float* bo1 = (const float*)d_in[10];
    const float* Wo2 = (const float*)d_in[11];
    const float* bo2 = (const float*)d_in[12];

    float* out        = (float*)d_out;
    float* node_repr  = out;                                  // [50001, 256]
    float* graph_repr = out + (size_t)N_NODES * HD;           // [1000, 256]
    float* y          = graph_repr + (size_t)N_GRAPHS * HD;   // [1000, 1]

    float *buf0 = nullptr, *buf1 = nullptr;
    cudaGetSymbolAddress((void**)&buf0, g_buf0);
    cudaGetSymbolAddress((void**)&buf1, g_buf1);

    const int gemm_grid = (N_NODES + BM - 1) / BM;            // 782
    const int attn_grid = (N_NODES + 7) / 8;                  // 6251 (8 warps/block)

    // Layer 0 (K = 128)
    gemm_kernel<<<gemm_grid, 256>>>(x, W0, b0, buf0, 128);
    attn_kernel<<<attn_grid, 256>>>(buf0, a2a, buf1);
    // Layer 1 (K = 256)
    gemm_kernel<<<gemm_grid, 256>>>(buf1, W1, b1, buf0, 256);
    attn_kernel<<<attn_grid, 256>>>(buf0, a2a, buf1);
    // Layer 2 (K = 256) -> node_repr directly into d_out
    gemm_kernel<<<gemm_grid, 256>>>(buf1, W2, b2, buf0, 256);
    attn_kernel<<<attn_grid, 256>>>(buf0, a2a, node_repr);
    // Readout
    readout_kernel<<<N_GRAPHS, 256>>>(node_repr, Wo1, bo1, Wo2, bo2, graph_repr, y);
}

// round 4
// speedup vs baseline: 1.4609x; 1.4609x over previous
#include <cuda_runtime.h>
#include <cuda_bf16.h>
#include <math.h>
#include <stdint.h>

#define N_NODES   50001
#define N_NBRS    12
#define N_GRAPHS  1000
#define NEG_BIG   (-9000000000000000.0f)
#define HD        256           // heads(8) * dim(32)

// ---------------------------------------------------------------------------
// Scratch (static device globals)
// ---------------------------------------------------------------------------
__device__ float g_buf0[(size_t)N_NODES * HD];
__device__ float g_buf1[(size_t)N_NODES * HD];

// Pre-split bf16 weights, layout per layer: [chunk][n=256][k=16]
// layer0: 8 chunks (K=128), layer1/2: 16 chunks (K=256) -> 40 chunks total
#define WCH_ELEMS 4096                    // 256 * 16
#define WT_TOTAL  (40 * WCH_ELEMS)        // 163840
__device__ unsigned short g_wbh[WT_TOTAL];
__device__ unsigned short g_wbl[WT_TOTAL];

// ---------------------------------------------------------------------------
// helpers
// ---------------------------------------------------------------------------
__device__ __forceinline__ unsigned short f2bf(float v) {
    return __bfloat16_as_ushort(__float2bfloat16_rn(v));
}
__device__ __forceinline__ float bf2f(unsigned short u) {
    return __bfloat162float(__ushort_as_bfloat16(u));
}
// pack two floats into bf16x2 (x in low half)
__device__ __forceinline__ uint32_t pack_hi(float x, float y) {
    return (uint32_t)f2bf(x) | ((uint32_t)f2bf(y) << 16);
}

__device__ __forceinline__ void mma_bf16(float* d, const uint32_t* a, const uint32_t* b) {
    asm volatile(
        "mma.sync.aligned.m16n8k16.row.col.f32.bf16.bf16.f32 "
        "{%0,%1,%2,%3}, {%4,%5,%6,%7}, {%8,%9}, {%0,%1,%2,%3};"
        : "+f"(d[0]), "+f"(d[1]), "+f"(d[2]), "+f"(d[3])
        : "r"(a[0]), "r"(a[1]), "r"(a[2]), "r"(a[3]), "r"(b[0]), "r"(b[1]));
}

// ---------------------------------------------------------------------------
// Weight prep: split W into bf16 hi/lo, transposed to [chunk][n][k].
// ---------------------------------------------------------------------------
__global__ void prep_w(const float* __restrict__ W0, const float* __restrict__ W1,
                       const float* __restrict__ W2,
                       unsigned short* __restrict__ bh, unsigned short* __restrict__ bl)
{
    int idx = blockIdx.x * blockDim.x + threadIdx.x;
    if (idx >= WT_TOTAL) return;
    const float* W; int K, base;
    if (idx < 8 * WCH_ELEMS)       { W = W0; K = 128; base = 0; }
    else if (idx < 24 * WCH_ELEMS) { W = W1; K = 256; base = 8 * WCH_ELEMS; }
    else                           { W = W2; K = 256; base = 24 * WCH_ELEMS; }
    int e = idx - base;
    int chunk = e / WCH_ELEMS;
    int rem   = e & (WCH_ELEMS - 1);
    int n  = rem >> 4;          // 0..255 (= head*32 + o)
    int kk = rem & 15;
    int h = n >> 5, o = n & 31;
    int k = chunk * 16 + kk;
    float v = W[((size_t)h * K + k) * 32 + o];
    unsigned short hi = f2bf(v);
    unsigned short lo = f2bf(v - bf2f(hi));
    bh[idx] = hi;
    bl[idx] = lo;
}

// ---------------------------------------------------------------------------
// bf16 3-term split GEMM via mma.sync.
// CTA tile 128x128, 8 warps (2 m-slots x 4 n-slots), warp tile 64x32.
// K chunked by 16, smem double-buffered, one __syncthreads per chunk.
// C = A @ Bt^T + bias, row 0 -> NEG_BIG.
// ---------------------------------------------------------------------------
#define BM 128
#define BN 128
#define BK 16

__global__ __launch_bounds__(256)
void gemm_mma(const float* __restrict__ A,
              const unsigned short* __restrict__ wbh,
              const unsigned short* __restrict__ wbl,
              const float* __restrict__ bias, float* __restrict__ C,
              int K, int wbase)
{
    __shared__ __align__(16) unsigned short sAh[2][BM][BK];
    __shared__ __align__(16) unsigned short sAl[2][BM][BK];
    __shared__ __align__(16) unsigned short sBh[2][BN][BK];
    __shared__ __align__(16) unsigned short sBl[2][BN][BK];

    const int tid  = threadIdx.x;
    const int wid  = tid >> 5;
    const int lane = tid & 31;
    const int g    = lane >> 2;      // group id 0..7
    const int t4   = lane & 3;
    const int wm   = wid & 1;        // 0..1  -> 64-row slot
    const int wn   = wid >> 1;       // 0..3  -> 32-col slot
    const int row0 = blockIdx.x * BM;
    const int col0 = blockIdx.y * BN;
    const int nch  = K >> 4;

    float acc[4][4][4];
#pragma unroll
    for (int i = 0; i < 4; i++)
#pragma unroll
        for (int j = 0; j < 4; j++)
#pragma unroll
            for (int q = 0; q < 4; q++) acc[i][j][q] = 0.0f;

    // prefetch registers
    float4 pa[2];
    uint4  pbh, pbl;

    // ---- load chunk `c` from gmem into regs ----
    auto load_regs = [&](int c) {
        int k0 = c * BK;
#pragma unroll
        for (int i = 0; i < 2; i++) {
            int j = tid + i * 256;            // 0..511
            int r = j >> 2, kq = j & 3;
            int gr = row0 + r;
            pa[i] = make_float4(0.f, 0.f, 0.f, 0.f);
            if (gr < N_NODES)
                pa[i] = *(const float4*)(A + (size_t)gr * K + k0 + kq * 4);
        }
        const uint4* sh = (const uint4*)(wbh + wbase + c * WCH_ELEMS + col0 * BK);
        const uint4* sl = (const uint4*)(wbl + wbase + c * WCH_ELEMS + col0 * BK);
        pbh = sh[tid];
        pbl = sl[tid];
    };

    // ---- store regs into smem stage s ----
    auto store_stage = [&](int s) {
#pragma unroll
        for (int i = 0; i < 2; i++) {
            int j = tid + i * 256;
            int r = j >> 2, kq = j & 3;
            float4 v = pa[i];
            float hx = bf2f(f2bf(v.x)), hy = bf2f(f2bf(v.y));
            float hz = bf2f(f2bf(v.z)), hw = bf2f(f2bf(v.w));
            uint2 hpack, lpack;
            hpack.x = pack_hi(v.x, v.y);
            hpack.y = pack_hi(v.z, v.w);
            lpack.x = pack_hi(v.x - hx, v.y - hy);
            lpack.y = pack_hi(v.z - hz, v.w - hw);
            *(uint2*)&sAh[s][r][kq * 4] = hpack;
            *(uint2*)&sAl[s][r][kq * 4] = lpack;
        }
        ((uint4*)sBh[s])[tid] = pbh;
        ((uint4*)sBl[s])[tid] = pbl;
    };

    load_regs(0);
    store_stage(0);
    __syncthreads();

    for (int c = 0; c < nch; c++) {
        int s = c & 1;
        bool more = (c + 1 < nch);
        if (more) load_regs(c + 1);

        // A fragments for this warp's 4 m-atoms (hi & lo)
        uint32_t ah[4][4], al[4][4];
#pragma unroll
        for (int ma = 0; ma < 4; ma++) {
            int r = wm * 64 + ma * 16 + g;
            ah[ma][0] = *(const uint32_t*)&sAh[s][r][t4 * 2];
            ah[ma][1] = *(const uint32_t*)&sAh[s][r + 8][t4 * 2];
            ah[ma][2] = *(const uint32_t*)&sAh[s][r][t4 * 2 + 8];
            ah[ma][3] = *(const uint32_t*)&sAh[s][r + 8][t4 * 2 + 8];
            al[ma][0] = *(const uint32_t*)&sAl[s][r][t4 * 2];
            al[ma][1] = *(const uint32_t*)&sAl[s][r + 8][t4 * 2];
            al[ma][2] = *(const uint32_t*)&sAl[s][r][t4 * 2 + 8];
            al[ma][3] = *(const uint32_t*)&sAl[s][r + 8][t4 * 2 + 8];
        }
#pragma unroll
        for (int na = 0; na < 4; na++) {
            int n = wn * 32 + na * 8 + g;
            uint32_t bhf[2], blf[2];
            bhf[0] = *(const uint32_t*)&sBh[s][n][t4 * 2];
            bhf[1] = *(const uint32_t*)&sBh[s][n][t4 * 2 + 8];
            blf[0] = *(const uint32_t*)&sBl[s][n][t4 * 2];
            blf[1] = *(const uint32_t*)&sBl[s][n][t4 * 2 + 8];
#pragma unroll
            for (int ma = 0; ma < 4; ma++) {
                mma_bf16(acc[ma][na], ah[ma], bhf);   // hi * hi
                mma_bf16(acc[ma][na], ah[ma], blf);   // hi * lo
                mma_bf16(acc[ma][na], al[ma], bhf);   // lo * hi
            }
        }

        if (more) store_stage(s ^ 1);
        __syncthreads();
    }

    // ---- epilogue: bias, row0 -> NEG_BIG, float2 stores ----
#pragma unroll
    for (int ma = 0; ma < 4; ma++) {
#pragma unroll
        for (int na = 0; na < 4; na++) {
            int cg = col0 + wn * 32 + na * 8 + t4 * 2;
            float bx = __ldg(&bias[cg]);
            float by = __ldg(&bias[cg + 1]);
            int r1 = row0 + wm * 64 + ma * 16 + g;
            int r2 = r1 + 8;
            if (r1 < N_NODES) {
                float2 v = make_float2(acc[ma][na][0] + bx, acc[ma][na][1] + by);
                if (r1 == 0) v = make_float2(NEG_BIG, NEG_BIG);
                *(float2*)(C + (size_t)r1 * HD + cg) = v;
            }
            if (r2 < N_NODES) {
                float2 v = make_float2(acc[ma][na][2] + bx, acc[ma][na][3] + by);
                *(float2*)(C + (size_t)r2 * HD + cg) = v;
            }
        }
    }
}

// ---------------------------------------------------------------------------
// Attention: one warp per node (unchanged — near its L2 floor).
// ---------------------------------------------------------------------------
__global__ __launch_bounds__(256)
void attn_kernel(const float* __restrict__ H, const int* __restrict__ a2a32,
                 float* __restrict__ out)
{
    const int gwarp = (blockIdx.x * blockDim.x + threadIdx.x) >> 5;
    if (gwarp >= N_NODES) return;
    const int node = gwarp;
    const int lane = threadIdx.x & 31;
    const int head = lane >> 2;
    const int part = lane & 3;

    const bool idx64 = ((a2a32[1] | a2a32[3] | a2a32[5] | a2a32[7]) == 0);

    const int off = head * 32 + part * 8;
    const float* hrow = H + (size_t)node * HD + off;
    float4 u0 = *(const float4*)hrow;
    float4 u1 = *(const float4*)(hrow + 4);
    float hn[8] = {u0.x, u0.y, u0.z, u0.w, u1.x, u1.y, u1.z, u1.w};

    float s = 0.f;
#pragma unroll
    for (int i = 0; i < 8; i++) s = fmaf(hn[i], hn[i], s);
    s += __shfl_xor_sync(0xffffffffu, s, 1);
    s += __shfl_xor_sync(0xffffffffu, s, 2);

    const float s0 = s;
    float m = s, ssum = 1.0f;

#pragma unroll
    for (int k = 0; k < N_NBRS; k++) {
        int li = node * N_NBRS + k;
        int idx = idx64 ? a2a32[2 * li] : a2a32[li];
        const float* nrow = H + (size_t)idx * HD + off;
        float4 v0 = *(const float4*)nrow;
        float4 v1 = *(const float4*)(nrow + 4);
        float d = hn[0] * v0.x;
        d = fmaf(hn[1], v0.y, d);
        d = fmaf(hn[2], v0.z, d);
        d = fmaf(hn[3], v0.w, d);
        d = fmaf(hn[4], v1.x, d);
        d = fmaf(hn[5], v1.y, d);
        d = fmaf(hn[6], v1.z, d);
        d = fmaf(hn[7], v1.w, d);
        d += __shfl_xor_sync(0xffffffffu, d, 1);
        d += __shfl_xor_sync(0xffffffffu, d, 2);
        float nm = fmaxf(m, d);
        ssum = ssum * expf(m - nm) + expf(d - nm);
        m = nm;
    }

    float attn0 = expf(s0 - m) / ssum;
    if (node == 0) attn0 = 0.0f;

    float* orow = out + (size_t)node * HD + off;
    *(float4*)orow       = make_float4(hn[0] * attn0, hn[1] * attn0, hn[2] * attn0, hn[3] * attn0);
    *(float4*)(orow + 4) = make_float4(hn[4] * attn0, hn[5] * attn0, hn[6] * attn0, hn[7] * attn0);
}

// ---------------------------------------------------------------------------
// Readout (unchanged)
// ---------------------------------------------------------------------------
__global__ __launch_bounds__(256)
void readout_kernel(const float* __restrict__ node_repr,
                    const float* __restrict__ Wo1, const float* __restrict__ bo1,
                    const float* __restrict__ Wo2, const float* __restrict__ bo2,
                    float* __restrict__ graph_repr, float* __restrict__ y)
{
    __shared__ float g[HD];
    const int gi = blockIdx.x;
    const int c  = threadIdx.x;

    float ssum = 0.f;
    const float* base = node_repr + (size_t)(1 + gi * 50) * HD + c;
#pragma unroll 10
    for (int r = 0; r < 50; r++) ssum += base[(size_t)r * HD];
    g[c] = ssum;
    graph_repr[(size_t)gi * HD + c] = ssum;
    __syncthreads();

    if (c < 32) {
        float acc = bo1[c];
#pragma unroll 8
        for (int d = 0; d < HD; d++) acc = fmaf(g[d], Wo1[d * 32 + c], acc);
        acc = fmaxf(acc, 0.0f);
        float val = acc * Wo2[c];
#pragma unroll
        for (int o = 16; o > 0; o >>= 1)
            val += __shfl_xor_sync(0xffffffffu, val, o);
        if (c == 0) y[gi] = val + bo2[0];
    }
}

// ---------------------------------------------------------------------------
extern "C" void kernel_launch(void* const* d_in, const int* in_sizes, int n_in,
                              void* d_out, int out_size)
{
    const float* x   = (const float*)d_in[0];
    const int*   a2a = (const int*)d_in[1];
    const float* W0  = (const float*)d_in[3];
    const float* b0  = (const float*)d_in[4];
    const float* W1  = (const float*)d_in[5];
    const float* b1  = (const float*)d_in[6];
    const float* W2  = (const float*)d_in[7];
    const float* b2  = (const float*)d_in[8];
    const float* Wo1 = (const float*)d_in[9];
    const float* bo1 = (const float*)d_in[10];
    const float* Wo2 = (const float*)d_in[11];
    const float* bo2 = (const float*)d_in[12];

    float* out        = (float*)d_out;
    float* node_repr  = out;
    float* graph_repr = out + (size_t)N_NODES * HD;
    float* y          = graph_repr + (size_t)N_GRAPHS * HD;

    float *buf0 = nullptr, *buf1 = nullptr;
    unsigned short *wbh = nullptr, *wbl = nullptr;
    cudaGetSymbolAddress((void**)&buf0, g_buf0);
    cudaGetSymbolAddress((void**)&buf1, g_buf1);
    cudaGetSymbolAddress((void**)&wbh, g_wbh);
    cudaGetSymbolAddress((void**)&wbl, g_wbl);

    dim3 ggrid((N_NODES + BM - 1) / BM, 2);        // 391 x 2
    const int attn_grid = (N_NODES + 7) / 8;       // 6251

    prep_w<<<(WT_TOTAL + 255) / 256, 256>>>(W0, W1, W2, wbh, wbl);

    gemm_mma<<<ggrid, 256>>>(x,    wbh, wbl, b0, buf0, 128, 0);
    attn_kernel<<<attn_grid, 256>>>(buf0, a2a, buf1);
    gemm_mma<<<ggrid, 256>>>(buf1, wbh, wbl, b1, buf0, 256, 8 * WCH_ELEMS);
    attn_kernel<<<attn_grid, 256>>>(buf0, a2a, buf1);
    gemm_mma<<<ggrid, 256>>>(buf1, wbh, wbl, b2, buf0, 256, 24 * WCH_ELEMS);
    attn_kernel<<<attn_grid, 256>>>(buf0, a2a, node_repr);

    readout_kernel<<<N_GRAPHS, 256>>>(node_repr, Wo1, bo1, Wo2, bo2, graph_repr, y);
}

// round 5
// speedup vs baseline: 1.8382x; 1.2582x over previous
#include <cuda_runtime.h>
#include <cuda_bf16.h>
#include <math.h>
#include <stdint.h>

#define N_NODES   50001
#define N_PAD     (N_NODES + 128)
#define N_NBRS    12
#define N_GRAPHS  1000
#define NEG_BIG   (-9000000000000000.0f)
#define HD        256

// ---------------------------------------------------------------------------
// Scratch
// ---------------------------------------------------------------------------
__device__ float g_bufH[(size_t)N_NODES * HD];                  // GEMM out (fp32)
__device__ unsigned short g_ah[(size_t)N_PAD * HD];             // A hi (bf16)
__device__ unsigned short g_al[(size_t)N_PAD * HD];             // A lo (bf16)

// Weights, layout per layer: [chunk32][n=256][k=32] bf16 hi/lo
// layer0: 4 chunks (K=128), layer1/2: 8 chunks -> 20 chunks total
#define WCH 8192                          // 256*32
#define WT_TOTAL (20 * WCH)
__device__ unsigned short g_wbh[WT_TOTAL];
__device__ unsigned short g_wbl[WT_TOTAL];

// ---------------------------------------------------------------------------
// helpers
// ---------------------------------------------------------------------------
__device__ __forceinline__ unsigned short f2bf(float v) {
    return __bfloat16_as_ushort(__float2bfloat16_rn(v));
}
__device__ __forceinline__ float bf2f(unsigned short u) {
    return __bfloat162float(__ushort_as_bfloat16(u));
}
__device__ __forceinline__ uint32_t pack2(unsigned short a, unsigned short b) {
    return (uint32_t)a | ((uint32_t)b << 16);
}

__device__ __forceinline__ void mma_bf16(float* d, const uint32_t* a, const uint32_t* b) {
    asm volatile(
        "mma.sync.aligned.m16n8k16.row.col.f32.bf16.bf16.f32 "
        "{%0,%1,%2,%3}, {%4,%5,%6,%7}, {%8,%9}, {%0,%1,%2,%3};"
        : "+f"(d[0]), "+f"(d[1]), "+f"(d[2]), "+f"(d[3])
        : "r"(a[0]), "r"(a[1]), "r"(a[2]), "r"(a[3]), "r"(b[0]), "r"(b[1]));
}
#define LDMX4(r, addr) \
    asm volatile("ldmatrix.sync.aligned.m8n8.x4.shared.b16 {%0,%1,%2,%3}, [%4];" \
        : "=r"((r)[0]), "=r"((r)[1]), "=r"((r)[2]), "=r"((r)[3]) : "r"(addr))
#define CP16(dst, src) \
    asm volatile("cp.async.cg.shared.global [%0], [%1], 16;" :: "r"(dst), "l"(src) : "memory")
#define CPCOMMIT() asm volatile("cp.async.commit_group;" ::: "memory")
#define CPWAIT1()  asm volatile("cp.async.wait_group 1;" ::: "memory")
#define CPWAIT0()  asm volatile("cp.async.wait_group 0;" ::: "memory")

// ---------------------------------------------------------------------------
// Weight prep: bf16 hi/lo split, [chunk32][n][k32]
// ---------------------------------------------------------------------------
__global__ void prep_w(const float* __restrict__ W0, const float* __restrict__ W1,
                       const float* __restrict__ W2,
                       unsigned short* __restrict__ bh, unsigned short* __restrict__ bl)
{
    int idx = blockIdx.x * blockDim.x + threadIdx.x;
    if (idx >= WT_TOTAL) return;
    const float* W; int K, base;
    if (idx < 4 * WCH)       { W = W0; K = 128; base = 0; }
    else if (idx < 12 * WCH) { W = W1; K = 256; base = 4 * WCH; }
    else                     { W = W2; K = 256; base = 12 * WCH; }
    int e = idx - base;
    int chunk = e >> 13;
    int rem   = e & 8191;
    int n  = rem >> 5;
    int kk = rem & 31;
    int h = n >> 5, o = n & 31;
    int k = chunk * 32 + kk;
    float v = W[((size_t)h * K + k) * 32 + o];
    unsigned short hi = f2bf(v);
    bh[idx] = hi;
    bl[idx] = f2bf(v - bf2f(hi));
}

// ---------------------------------------------------------------------------
// split_x: fp32 x -> bf16 hi/lo  (layer-0 A), K=128
// ---------------------------------------------------------------------------
__global__ void split_x(const float* __restrict__ x,
                        unsigned short* __restrict__ ah, unsigned short* __restrict__ al)
{
    int i = blockIdx.x * blockDim.x + threadIdx.x;              // float4 index
    if (i * 4 >= N_NODES * 128) return;
    float4 v = *(const float4*)(x + i * 4);
    unsigned short hx = f2bf(v.x), hy = f2bf(v.y), hz = f2bf(v.z), hw = f2bf(v.w);
    uint2 hp, lp;
    hp.x = pack2(hx, hy); hp.y = pack2(hz, hw);
    lp.x = pack2(f2bf(v.x - bf2f(hx)), f2bf(v.y - bf2f(hy)));
    lp.y = pack2(f2bf(v.z - bf2f(hz)), f2bf(v.w - bf2f(hw)));
    *(uint2*)(ah + i * 4) = hp;
    *(uint2*)(al + i * 4) = lp;
}

// ---------------------------------------------------------------------------
// bf16 3-term split GEMM: cp.async 2-stage, ldmatrix, 80B-padded smem rows.
// CTA 128x128, 8 warps (2m x 4n), warp 64x32. BK=32.
// ---------------------------------------------------------------------------
#define SROW 80                       // bytes per smem row (40 halves)
#define SARR 10240                    // bytes per array (128 rows * 80B)
#define SMEM_BYTES (8 * SARR)         // 2 stages * 4 arrays

__global__ __launch_bounds__(256, 2)
void gemm_mma(const unsigned short* __restrict__ Ah, const unsigned short* __restrict__ Al,
              const unsigned short* __restrict__ wbh, const unsigned short* __restrict__ wbl,
              const float* __restrict__ bias, float* __restrict__ C, int K, int wbase)
{
    extern __shared__ char smem[];
    const uint32_t sbase = (uint32_t)__cvta_generic_to_shared(smem);

    const int tid  = threadIdx.x;
    const int wid  = tid >> 5;
    const int lane = tid & 31;
    const int g    = lane >> 2;
    const int t4   = lane & 3;
    const int wm   = wid & 1;
    const int wn   = wid >> 1;
    const int row0 = blockIdx.x * 128;
    const int col0 = blockIdx.y * 128;
    const int nch  = K >> 5;

    // per-thread cp.async indices: j in {tid, tid+256}: row=j>>2, seg=j&3
    const int r_a  = tid >> 2, seg_a = tid & 3;

    // ldmatrix lane offsets
    const uint32_t aro = ((((lane >> 3) & 1) * 8 + (lane & 7)) * SROW) + ((lane >> 4) * 16);
    const uint32_t bro = ((((lane >> 4) & 1) * 8 + (lane & 7)) * SROW) + (((lane >> 3) & 1) * 16);

    auto fill = [&](int s, int c) {
        uint32_t stA = sbase + (s * 4) * SARR;
        uint32_t stB = sbase + (s * 4 + 2) * SARR;
        const unsigned short* srcB = wbh + wbase + c * WCH + (col0 << 5);
        const unsigned short* srcBl = wbl + wbase + c * WCH + (col0 << 5);
#pragma unroll
        for (int i = 0; i < 2; i++) {
            int row = r_a + i * 64, seg = seg_a;
            size_t aoff = (size_t)(row0 + row) * K + c * 32 + seg * 8;
            uint32_t d = stA + row * SROW + seg * 16;
            CP16(d,        Ah + aoff);
            CP16(d + SARR, Al + aoff);
            size_t boff = (size_t)row * 32 + seg * 8;
            uint32_t db = stB + row * SROW + seg * 16;
            CP16(db,        srcB  + boff);
            CP16(db + SARR, srcBl + boff);
        }
    };

    float acc[4][4][4];
#pragma unroll
    for (int i = 0; i < 4; i++)
#pragma unroll
        for (int j = 0; j < 4; j++)
#pragma unroll
            for (int q = 0; q < 4; q++) acc[i][j][q] = 0.0f;

    fill(0, 0);
    CPCOMMIT();

    for (int c = 0; c < nch; c++) {
        int s = c & 1;
        if (c + 1 < nch) { fill(s ^ 1, c + 1); CPCOMMIT(); CPWAIT1(); }
        else             { CPWAIT0(); }
        __syncthreads();

        uint32_t stAh = sbase + (s * 4) * SARR + (wm * 64) * SROW + aro;
        uint32_t stAl = stAh + SARR;
        uint32_t stBh = sbase + (s * 4 + 2) * SARR + (wn * 32) * SROW + bro;
        uint32_t stBl = stBh + SARR;

#pragma unroll
        for (int k16 = 0; k16 < 2; k16++) {
            uint32_t ko = k16 * 32;
            uint32_t ah[4][4], al[4][4], bh4[2][4], bl4[2][4];
#pragma unroll
            for (int ma = 0; ma < 4; ma++) {
                LDMX4(ah[ma], stAh + ma * 16 * SROW + ko);
                LDMX4(al[ma], stAl + ma * 16 * SROW + ko);
            }
#pragma unroll
            for (int np = 0; np < 2; np++) {
                LDMX4(bh4[np], stBh + np * 16 * SROW + ko);
                LDMX4(bl4[np], stBl + np * 16 * SROW + ko);
            }
#pragma unroll
            for (int na = 0; na < 4; na++) {
                uint32_t bhf[2] = { bh4[na >> 1][(na & 1) * 2], bh4[na >> 1][(na & 1) * 2 + 1] };
                uint32_t blf[2] = { bl4[na >> 1][(na & 1) * 2], bl4[na >> 1][(na & 1) * 2 + 1] };
#pragma unroll
                for (int ma = 0; ma < 4; ma++) {
                    mma_bf16(acc[ma][na], ah[ma], bhf);
                    mma_bf16(acc[ma][na], ah[ma], blf);
                    mma_bf16(acc[ma][na], al[ma], bhf);
                }
            }
        }
        __syncthreads();
    }

    // epilogue
#pragma unroll
    for (int ma = 0; ma < 4; ma++) {
#pragma unroll
        for (int na = 0; na < 4; na++) {
            int cg = col0 + wn * 32 + na * 8 + t4 * 2;
            float bx = __ldg(&bias[cg]);
            float by = __ldg(&bias[cg + 1]);
            int r1 = row0 + wm * 64 + ma * 16 + g;
            int r2 = r1 + 8;
            if (r1 < N_NODES) {
                float2 v = make_float2(acc[ma][na][0] + bx, acc[ma][na][1] + by);
                if (r1 == 0) v = make_float2(NEG_BIG, NEG_BIG);
                *(float2*)(C + (size_t)r1 * HD + cg) = v;
            }
            if (r2 < N_NODES) {
                float2 v = make_float2(acc[ma][na][2] + bx, acc[ma][na][3] + by);
                *(float2*)(C + (size_t)r2 * HD + cg) = v;
            }
        }
    }
}

// ---------------------------------------------------------------------------
// Attention: one warp per node. Writes bf16 hi/lo (layers 0,1) or fp32 (final).
// ---------------------------------------------------------------------------
__global__ __launch_bounds__(256)
void attn_kernel(const float* __restrict__ H, const int* __restrict__ a2a32,
                 unsigned short* __restrict__ outh, unsigned short* __restrict__ outl,
                 float* __restrict__ outf)
{
    const int gwarp = (blockIdx.x * blockDim.x + threadIdx.x) >> 5;
    if (gwarp >= N_NODES) return;
    const int node = gwarp;
    const int lane = threadIdx.x & 31;
    const int head = lane >> 2;
    const int part = lane & 3;

    const bool idx64 = ((a2a32[1] | a2a32[3] | a2a32[5] | a2a32[7]) == 0);

    const int off = head * 32 + part * 8;
    const float* hrow = H + (size_t)node * HD + off;
    float4 u0 = *(const float4*)hrow;
    float4 u1 = *(const float4*)(hrow + 4);
    float hn[8] = {u0.x, u0.y, u0.z, u0.w, u1.x, u1.y, u1.z, u1.w};

    float s = 0.f;
#pragma unroll
    for (int i = 0; i < 8; i++) s = fmaf(hn[i], hn[i], s);
    s += __shfl_xor_sync(0xffffffffu, s, 1);
    s += __shfl_xor_sync(0xffffffffu, s, 2);

    const float s0 = s;
    float m = s, ssum = 1.0f;

#pragma unroll
    for (int k = 0; k < N_NBRS; k++) {
        int li = node * N_NBRS + k;
        int idx = idx64 ? a2a32[2 * li] : a2a32[li];
        const float* nrow = H + (size_t)idx * HD + off;
        float4 v0 = *(const float4*)nrow;
        float4 v1 = *(const float4*)(nrow + 4);
        float d = hn[0] * v0.x;
        d = fmaf(hn[1], v0.y, d);
        d = fmaf(hn[2], v0.z, d);
        d = fmaf(hn[3], v0.w, d);
        d = fmaf(hn[4], v1.x, d);
        d = fmaf(hn[5], v1.y, d);
        d = fmaf(hn[6], v1.z, d);
        d = fmaf(hn[7], v1.w, d);
        d += __shfl_xor_sync(0xffffffffu, d, 1);
        d += __shfl_xor_sync(0xffffffffu, d, 2);
        float nm = fmaxf(m, d);
        ssum = ssum * expf(m - nm) + expf(d - nm);
        m = nm;
    }

    float attn0 = expf(s0 - m) / ssum;
    if (node == 0) attn0 = 0.0f;

    float v[8];
#pragma unroll
    for (int i = 0; i < 8; i++) v[i] = hn[i] * attn0;

    if (outf) {
        float* orow = outf + (size_t)node * HD + off;
        *(float4*)orow       = make_float4(v[0], v[1], v[2], v[3]);
        *(float4*)(orow + 4) = make_float4(v[4], v[5], v[6], v[7]);
    } else {
        unsigned short hh[8];
        uint4 hp, lp;
#pragma unroll
        for (int i = 0; i < 8; i++) hh[i] = f2bf(v[i]);
        hp.x = pack2(hh[0], hh[1]); hp.y = pack2(hh[2], hh[3]);
        hp.z = pack2(hh[4], hh[5]); hp.w = pack2(hh[6], hh[7]);
        lp.x = pack2(f2bf(v[0] - bf2f(hh[0])), f2bf(v[1] - bf2f(hh[1])));
        lp.y = pack2(f2bf(v[2] - bf2f(hh[2])), f2bf(v[3] - bf2f(hh[3])));
        lp.z = pack2(f2bf(v[4] - bf2f(hh[4])), f2bf(v[5] - bf2f(hh[5])));
        lp.w = pack2(f2bf(v[6] - bf2f(hh[6])), f2bf(v[7] - bf2f(hh[7])));
        *(uint4*)(outh + (size_t)node * HD + off) = hp;
        *(uint4*)(outl + (size_t)node * HD + off) = lp;
    }
}

// ---------------------------------------------------------------------------
// Readout
// ---------------------------------------------------------------------------
__global__ __launch_bounds__(256)
void readout_kernel(const float* __restrict__ node_repr,
                    const float* __restrict__ Wo1, const float* __restrict__ bo1,
                    const float* __restrict__ Wo2, const float* __restrict__ bo2,
                    float* __restrict__ graph_repr, float* __restrict__ y)
{
    __shared__ float g[HD];
    const int gi = blockIdx.x;
    const int c  = threadIdx.x;

    float ssum = 0.f;
    const float* base = node_repr + (size_t)(1 + gi * 50) * HD + c;
#pragma unroll 10
    for (int r = 0; r < 50; r++) ssum += base[(size_t)r * HD];
    g[c] = ssum;
    graph_repr[(size_t)gi * HD + c] = ssum;
    __syncthreads();

    if (c < 32) {
        float acc = bo1[c];
#pragma unroll 8
        for (int d = 0; d < HD; d++) acc = fmaf(g[d], Wo1[d * 32 + c], acc);
        acc = fmaxf(acc, 0.0f);
        float val = acc * Wo2[c];
#pragma unroll
        for (int o = 16; o > 0; o >>= 1)
            val += __shfl_xor_sync(0xffffffffu, val, o);
        if (c == 0) y[gi] = val + bo2[0];
    }
}

// ---------------------------------------------------------------------------
extern "C" void kernel_launch(void* const* d_in, const int* in_sizes, int n_in,
                              void* d_out, int out_size)
{
    const float* x   = (const float*)d_in[0];
    const int*   a2a = (const int*)d_in[1];
    const float* W0  = (const float*)d_in[3];
    const float* b0  = (const float*)d_in[4];
    const float* W1  = (const float*)d_in[5];
    const float* b1  = (const float*)d_in[6];
    const float* W2  = (const float*)d_in[7];
    const float* b2  = (const float*)d_in[8];
    const float* Wo1 = (const float*)d_in[9];
    const float* bo1 = (const float*)d_in[10];
    const float* Wo2 = (const float*)d_in[11];
    const float* bo2 = (const float*)d_in[12];

    float* out        = (float*)d_out;
    float* node_repr  = out;
    float* graph_repr = out + (size_t)N_NODES * HD;
    float* y          = graph_repr + (size_t)N_GRAPHS * HD;

    float* bufH = nullptr;
    unsigned short *ah = nullptr, *al = nullptr, *wbh = nullptr, *wbl = nullptr;
    cudaGetSymbolAddress((void**)&bufH, g_bufH);
    cudaGetSymbolAddress((void**)&ah, g_ah);
    cudaGetSymbolAddress((void**)&al, g_al);
    cudaGetSymbolAddress((void**)&wbh, g_wbh);
    cudaGetSymbolAddress((void**)&wbl, g_wbl);

    cudaFuncSetAttribute(gemm_mma, cudaFuncAttributeMaxDynamicSharedMemorySize, SMEM_BYTES);

    dim3 ggrid((N_NODES + 127) / 128, 2);
    const int attn_grid = (N_NODES + 7) / 8;

    prep_w<<<(WT_TOTAL + 255) / 256, 256>>>(W0, W1, W2, wbh, wbl);
    split_x<<<(N_NODES * 128 / 4 + 255) / 256, 256>>>(x, ah, al);

    gemm_mma<<<ggrid, 256, SMEM_BYTES>>>(ah, al, wbh, wbl, b0, bufH, 128, 0);
    attn_kernel<<<attn_grid, 256>>>(bufH, a2a, ah, al, nullptr);
    gemm_mma<<<ggrid, 256, SMEM_BYTES>>>(ah, al, wbh, wbl, b1, bufH, 256, 4 * WCH);
    attn_kernel<<<attn_grid, 256>>>(bufH, a2a, ah, al, nullptr);
    gemm_mma<<<ggrid, 256, SMEM_BYTES>>>(ah, al, wbh, wbl, b2, bufH, 256, 12 * WCH);
    attn_kernel<<<attn_grid, 256>>>(bufH, a2a, nullptr, nullptr, node_repr);

    readout_kernel<<<N_GRAPHS, 256>>>(node_repr, Wo1, bo1, Wo2, bo2, graph_repr, y);
}

// round 6
// speedup vs baseline: 1.9010x; 1.0342x over previous
#include <cuda_runtime.h>
#include <cuda_bf16.h>
#include <math.h>
#include <stdint.h>

#define N_NODES   50001
#define N_PAD     (N_NODES + 128)
#define N_NBRS    12
#define N_GRAPHS  1000
#define NEG_BIG   (-9000000000000000.0f)
#define HD        256

// ---------------------------------------------------------------------------
// Scratch
// ---------------------------------------------------------------------------
__device__ float g_bufH[(size_t)N_NODES * HD];                  // GEMM out (fp32)
__device__ unsigned short g_nbh[(size_t)N_PAD * HD];            // GEMM out (bf16 hi) for gather
__device__ unsigned short g_ah[(size_t)N_PAD * HD];             // next-layer A hi (bf16)
__device__ unsigned short g_al[(size_t)N_PAD * HD];             // next-layer A lo (bf16)

// Weights, layout per layer: [chunk32][n=256][k=32] bf16 hi/lo
#define WCH 8192                          // 256*32
#define WT_TOTAL (20 * WCH)
__device__ unsigned short g_wbh[WT_TOTAL];
__device__ unsigned short g_wbl[WT_TOTAL];

// ---------------------------------------------------------------------------
// helpers
// ---------------------------------------------------------------------------
__device__ __forceinline__ unsigned short f2bf(float v) {
    return __bfloat16_as_ushort(__float2bfloat16_rn(v));
}
__device__ __forceinline__ float bf2f(unsigned short u) {
    return __bfloat162float(__ushort_as_bfloat16(u));
}
__device__ __forceinline__ uint32_t pack2(unsigned short a, unsigned short b) {
    return (uint32_t)a | ((uint32_t)b << 16);
}
__device__ __forceinline__ float2 bf2x2(uint32_t u) {
    float2 r;
    r.x = bf2f((unsigned short)(u & 0xffff));
    r.y = bf2f((unsigned short)(u >> 16));
    return r;
}

__device__ __forceinline__ void mma_bf16(float* d, const uint32_t* a, const uint32_t* b) {
    asm volatile(
        "mma.sync.aligned.m16n8k16.row.col.f32.bf16.bf16.f32 "
        "{%0,%1,%2,%3}, {%4,%5,%6,%7}, {%8,%9}, {%0,%1,%2,%3};"
        : "+f"(d[0]), "+f"(d[1]), "+f"(d[2]), "+f"(d[3])
        : "r"(a[0]), "r"(a[1]), "r"(a[2]), "r"(a[3]), "r"(b[0]), "r"(b[1]));
}
#define LDMX4(r, addr) \
    asm volatile("ldmatrix.sync.aligned.m8n8.x4.shared.b16 {%0,%1,%2,%3}, [%4];" \
        : "=r"((r)[0]), "=r"((r)[1]), "=r"((r)[2]), "=r"((r)[3]) : "r"(addr))
#define CP16(dst, src) \
    asm volatile("cp.async.cg.shared.global [%0], [%1], 16;" :: "r"(dst), "l"(src) : "memory")
#define CPCOMMIT() asm volatile("cp.async.commit_group;" ::: "memory")
#define CPWAIT1()  asm volatile("cp.async.wait_group 1;" ::: "memory")
#define CPWAIT0()  asm volatile("cp.async.wait_group 0;" ::: "memory")

// ---------------------------------------------------------------------------
// Weight prep
// ---------------------------------------------------------------------------
__global__ void prep_w(const float* __restrict__ W0, const float* __restrict__ W1,
                       const float* __restrict__ W2,
                       unsigned short* __restrict__ bh, unsigned short* __restrict__ bl)
{
    int idx = blockIdx.x * blockDim.x + threadIdx.x;
    if (idx >= WT_TOTAL) return;
    const float* W; int K, base;
    if (idx < 4 * WCH)       { W = W0; K = 128; base = 0; }
    else if (idx < 12 * WCH) { W = W1; K = 256; base = 4 * WCH; }
    else                     { W = W2; K = 256; base = 12 * WCH; }
    int e = idx - base;
    int chunk = e >> 13;
    int rem   = e & 8191;
    int n  = rem >> 5;
    int kk = rem & 31;
    int h = n >> 5, o = n & 31;
    int k = chunk * 32 + kk;
    float v = W[((size_t)h * K + k) * 32 + o];
    unsigned short hi = f2bf(v);
    bh[idx] = hi;
    bl[idx] = f2bf(v - bf2f(hi));
}

// ---------------------------------------------------------------------------
// split_x: fp32 x -> bf16 hi/lo (layer-0 A)
// ---------------------------------------------------------------------------
__global__ void split_x(const float* __restrict__ x,
                        unsigned short* __restrict__ ah, unsigned short* __restrict__ al)
{
    int i = blockIdx.x * blockDim.x + threadIdx.x;
    if (i * 4 >= N_NODES * 128) return;
    float4 v = *(const float4*)(x + i * 4);
    unsigned short hx = f2bf(v.x), hy = f2bf(v.y), hz = f2bf(v.z), hw = f2bf(v.w);
    uint2 hp, lp;
    hp.x = pack2(hx, hy); hp.y = pack2(hz, hw);
    lp.x = pack2(f2bf(v.x - bf2f(hx)), f2bf(v.y - bf2f(hy)));
    lp.y = pack2(f2bf(v.z - bf2f(hz)), f2bf(v.w - bf2f(hw)));
    *(uint2*)(ah + i * 4) = hp;
    *(uint2*)(al + i * 4) = lp;
}

// ---------------------------------------------------------------------------
// GEMM (unchanged mainloop) + epilogue also writes bf16 copy for the gather
// ---------------------------------------------------------------------------
#define SROW 80
#define SARR 10240
#define SMEM_BYTES (8 * SARR)

__global__ __launch_bounds__(256, 2)
void gemm_mma(const unsigned short* __restrict__ Ah, const unsigned short* __restrict__ Al,
              const unsigned short* __restrict__ wbh, const unsigned short* __restrict__ wbl,
              const float* __restrict__ bias, float* __restrict__ C,
              unsigned short* __restrict__ NBH, int K, int wbase)
{
    extern __shared__ char smem[];
    const uint32_t sbase = (uint32_t)__cvta_generic_to_shared(smem);

    const int tid  = threadIdx.x;
    const int wid  = tid >> 5;
    const int lane = tid & 31;
    const int g    = lane >> 2;
    const int t4   = lane & 3;
    const int wm   = wid & 1;
    const int wn   = wid >> 1;
    const int row0 = blockIdx.x * 128;
    const int col0 = blockIdx.y * 128;
    const int nch  = K >> 5;

    const int r_a  = tid >> 2, seg_a = tid & 3;

    const uint32_t aro = ((((lane >> 3) & 1) * 8 + (lane & 7)) * SROW) + ((lane >> 4) * 16);
    const uint32_t bro = ((((lane >> 4) & 1) * 8 + (lane & 7)) * SROW) + (((lane >> 3) & 1) * 16);

    auto fill = [&](int s, int c) {
        uint32_t stA = sbase + (s * 4) * SARR;
        uint32_t stB = sbase + (s * 4 + 2) * SARR;
        const unsigned short* srcB  = wbh + wbase + c * WCH + (col0 << 5);
        const unsigned short* srcBl = wbl + wbase + c * WCH + (col0 << 5);
#pragma unroll
        for (int i = 0; i < 2; i++) {
            int row = r_a + i * 64, seg = seg_a;
            size_t aoff = (size_t)(row0 + row) * K + c * 32 + seg * 8;
            uint32_t d = stA + row * SROW + seg * 16;
            CP16(d,        Ah + aoff);
            CP16(d + SARR, Al + aoff);
            size_t boff = (size_t)row * 32 + seg * 8;
            uint32_t db = stB + row * SROW + seg * 16;
            CP16(db,        srcB  + boff);
            CP16(db + SARR, srcBl + boff);
        }
    };

    float acc[4][4][4];
#pragma unroll
    for (int i = 0; i < 4; i++)
#pragma unroll
        for (int j = 0; j < 4; j++)
#pragma unroll
            for (int q = 0; q < 4; q++) acc[i][j][q] = 0.0f;

    fill(0, 0);
    CPCOMMIT();

    for (int c = 0; c < nch; c++) {
        int s = c & 1;
        if (c + 1 < nch) { fill(s ^ 1, c + 1); CPCOMMIT(); CPWAIT1(); }
        else             { CPWAIT0(); }
        __syncthreads();

        uint32_t stAh = sbase + (s * 4) * SARR + (wm * 64) * SROW + aro;
        uint32_t stAl = stAh + SARR;
        uint32_t stBh = sbase + (s * 4 + 2) * SARR + (wn * 32) * SROW + bro;
        uint32_t stBl = stBh + SARR;

#pragma unroll
        for (int k16 = 0; k16 < 2; k16++) {
            uint32_t ko = k16 * 32;
            uint32_t ah[4][4], al[4][4], bh4[2][4], bl4[2][4];
#pragma unroll
            for (int ma = 0; ma < 4; ma++) {
                LDMX4(ah[ma], stAh + ma * 16 * SROW + ko);
                LDMX4(al[ma], stAl + ma * 16 * SROW + ko);
            }
#pragma unroll
            for (int np = 0; np < 2; np++) {
                LDMX4(bh4[np], stBh + np * 16 * SROW + ko);
                LDMX4(bl4[np], stBl + np * 16 * SROW + ko);
            }
#pragma unroll
            for (int na = 0; na < 4; na++) {
                uint32_t bhf[2] = { bh4[na >> 1][(na & 1) * 2], bh4[na >> 1][(na & 1) * 2 + 1] };
                uint32_t blf[2] = { bl4[na >> 1][(na & 1) * 2], bl4[na >> 1][(na & 1) * 2 + 1] };
#pragma unroll
                for (int ma = 0; ma < 4; ma++) {
                    mma_bf16(acc[ma][na], ah[ma], bhf);
                    mma_bf16(acc[ma][na], ah[ma], blf);
                    mma_bf16(acc[ma][na], al[ma], bhf);
                }
            }
        }
        __syncthreads();
    }

    // epilogue: fp32 + bf16-hi stores
#pragma unroll
    for (int ma = 0; ma < 4; ma++) {
#pragma unroll
        for (int na = 0; na < 4; na++) {
            int cg = col0 + wn * 32 + na * 8 + t4 * 2;
            float bx = __ldg(&bias[cg]);
            float by = __ldg(&bias[cg + 1]);
            int r1 = row0 + wm * 64 + ma * 16 + g;
            int r2 = r1 + 8;
            if (r1 < N_NODES) {
                float2 v = make_float2(acc[ma][na][0] + bx, acc[ma][na][1] + by);
                if (r1 == 0) v = make_float2(NEG_BIG, NEG_BIG);
                *(float2*)(C + (size_t)r1 * HD + cg) = v;
                *(uint32_t*)(NBH + (size_t)r1 * HD + cg) = pack2(f2bf(v.x), f2bf(v.y));
            }
            if (r2 < N_NODES) {
                float2 v = make_float2(acc[ma][na][2] + bx, acc[ma][na][3] + by);
                *(float2*)(C + (size_t)r2 * HD + cg) = v;
                *(uint32_t*)(NBH + (size_t)r2 * HD + cg) = pack2(f2bf(v.x), f2bf(v.y));
            }
        }
    }
}

// ---------------------------------------------------------------------------
// Attention: own row fp32, neighbors bf16 (half the gather bytes).
// Scores in registers, single max pass, 13 expf.
// ---------------------------------------------------------------------------
__global__ __launch_bounds__(256)
void attn_kernel(const float* __restrict__ H, const unsigned short* __restrict__ NBH,
                 const int* __restrict__ a2a32,
                 unsigned short* __restrict__ outh, unsigned short* __restrict__ outl,
                 float* __restrict__ outf)
{
    const int gwarp = (blockIdx.x * blockDim.x + threadIdx.x) >> 5;
    if (gwarp >= N_NODES) return;
    const int node = gwarp;
    const int lane = threadIdx.x & 31;
    const int head = lane >> 2;
    const int part = lane & 3;

    const bool idx64 = ((a2a32[1] | a2a32[3] | a2a32[5] | a2a32[7]) == 0);

    const int off = head * 32 + part * 8;
    const float* hrow = H + (size_t)node * HD + off;
    float4 u0 = *(const float4*)hrow;
    float4 u1 = *(const float4*)(hrow + 4);
    float hn[8] = {u0.x, u0.y, u0.z, u0.w, u1.x, u1.y, u1.z, u1.w};

    float s = 0.f;
#pragma unroll
    for (int i = 0; i < 8; i++) s = fmaf(hn[i], hn[i], s);
    s += __shfl_xor_sync(0xffffffffu, s, 1);
    s += __shfl_xor_sync(0xffffffffu, s, 2);
    const float s0 = s;

    float d[N_NBRS];
#pragma unroll
    for (int k = 0; k < N_NBRS; k++) {
        int li = node * N_NBRS + k;
        int idx = idx64 ? a2a32[2 * li] : a2a32[li];
        uint4 p = *(const uint4*)(NBH + (size_t)idx * HD + off);
        float2 f0 = bf2x2(p.x), f1 = bf2x2(p.y), f2c = bf2x2(p.z), f3 = bf2x2(p.w);
        float dd = hn[0] * f0.x;
        dd = fmaf(hn[1], f0.y, dd);
        dd = fmaf(hn[2], f1.x, dd);
        dd = fmaf(hn[3], f1.y, dd);
        dd = fmaf(hn[4], f2c.x, dd);
        dd = fmaf(hn[5], f2c.y, dd);
        dd = fmaf(hn[6], f3.x, dd);
        dd = fmaf(hn[7], f3.y, dd);
        dd += __shfl_xor_sync(0xffffffffu, dd, 1);
        dd += __shfl_xor_sync(0xffffffffu, dd, 2);
        d[k] = dd;
    }

    float m = s0;
#pragma unroll
    for (int k = 0; k < N_NBRS; k++) m = fmaxf(m, d[k]);
    float e0 = expf(s0 - m);
    float ssum = e0;
#pragma unroll
    for (int k = 0; k < N_NBRS; k++) ssum += expf(d[k] - m);

    float attn0 = e0 / ssum;
    if (node == 0) attn0 = 0.0f;

    float v[8];
#pragma unroll
    for (int i = 0; i < 8; i++) v[i] = hn[i] * attn0;

    if (outf) {
        float* orow = outf + (size_t)node * HD + off;
        *(float4*)orow       = make_float4(v[0], v[1], v[2], v[3]);
        *(float4*)(orow + 4) = make_float4(v[4], v[5], v[6], v[7]);
    } else {
        unsigned short hh[8];
        uint4 hp, lp;
#pragma unroll
        for (int i = 0; i < 8; i++) hh[i] = f2bf(v[i]);
        hp.x = pack2(hh[0], hh[1]); hp.y = pack2(hh[2], hh[3]);
        hp.z = pack2(hh[4], hh[5]); hp.w = pack2(hh[6], hh[7]);
        lp.x = pack2(f2bf(v[0] - bf2f(hh[0])), f2bf(v[1] - bf2f(hh[1])));
        lp.y = pack2(f2bf(v[2] - bf2f(hh[2])), f2bf(v[3] - bf2f(hh[3])));
        lp.z = pack2(f2bf(v[4] - bf2f(hh[4])), f2bf(v[5] - bf2f(hh[5])));
        lp.w = pack2(f2bf(v[6] - bf2f(hh[6])), f2bf(v[7] - bf2f(hh[7])));
        *(uint4*)(outh + (size_t)node * HD + off) = hp;
        *(uint4*)(outl + (size_t)node * HD + off) = lp;
    }
}

// ---------------------------------------------------------------------------
// Readout
// ---------------------------------------------------------------------------
__global__ __launch_bounds__(256)
void readout_kernel(const float* __restrict__ node_repr,
                    const float* __restrict__ Wo1, const float* __restrict__ bo1,
                    const float* __restrict__ Wo2, const float* __restrict__ bo2,
                    float* __restrict__ graph_repr, float* __restrict__ y)
{
    __shared__ float g[HD];
    const int gi = blockIdx.x;
    const int c  = threadIdx.x;

    float ssum = 0.f;
    const float* base = node_repr + (size_t)(1 + gi * 50) * HD + c;
#pragma unroll 10
    for (int r = 0; r < 50; r++) ssum += base[(size_t)r * HD];
    g[c] = ssum;
    graph_repr[(size_t)gi * HD + c] = ssum;
    __syncthreads();

    if (c < 32) {
        float acc = bo1[c];
#pragma unroll 8
        for (int d = 0; d < HD; d++) acc = fmaf(g[d], Wo1[d * 32 + c], acc);
        acc = fmaxf(acc, 0.0f);
        float val = acc * Wo2[c];
#pragma unroll
        for (int o = 16; o > 0; o >>= 1)
            val += __shfl_xor_sync(0xffffffffu, val, o);
        if (c == 0) y[gi] = val + bo2[0];
    }
}

// ---------------------------------------------------------------------------
extern "C" void kernel_launch(void* const* d_in, const int* in_sizes, int n_in,
                              void* d_out, int out_size)
{
    const float* x   = (const float*)d_in[0];
    const int*   a2a = (const int*)d_in[1];
    const float* W0  = (const float*)d_in[3];
    const float* b0  = (const float*)d_in[4];
    const float* W1  = (const float*)d_in[5];
    const float* b1  = (const float*)d_in[6];
    const float* W2  = (const float*)d_in[7];
    const float* b2  = (const float*)d_in[8];
    const float* Wo1 = (const float*)d_in[9];
    const float* bo1 = (const float*)d_in[10];
    const float* Wo2 = (const float*)d_in[11];
    const float* bo2 = (const float*)d_in[12];

    float* out        = (float*)d_out;
    float* node_repr  = out;
    float* graph_repr = out + (size_t)N_NODES * HD;
    float* y          = graph_repr + (size_t)N_GRAPHS * HD;

    float* bufH = nullptr;
    unsigned short *nbh = nullptr, *ah = nullptr, *al = nullptr, *wbh = nullptr, *wbl = nullptr;
    cudaGetSymbolAddress((void**)&bufH, g_bufH);
    cudaGetSymbolAddress((void**)&nbh, g_nbh);
    cudaGetSymbolAddress((void**)&ah, g_ah);
    cudaGetSymbolAddress((void**)&al, g_al);
    cudaGetSymbolAddress((void**)&wbh, g_wbh);
    cudaGetSymbolAddress((void**)&wbl, g_wbl);

    cudaFuncSetAttribute(gemm_mma, cudaFuncAttributeMaxDynamicSharedMemorySize, SMEM_BYTES);

    dim3 ggrid((N_NODES + 127) / 128, 2);
    const int attn_grid = (N_NODES + 7) / 8;

    prep_w<<<(WT_TOTAL + 255) / 256, 256>>>(W0, W1, W2, wbh, wbl);
    split_x<<<(N_NODES * 128 / 4 + 255) / 256, 256>>>(x, ah, al);

    gemm_mma<<<ggrid, 256, SMEM_BYTES>>>(ah, al, wbh, wbl, b0, bufH, nbh, 128, 0);
    attn_kernel<<<attn_grid, 256>>>(bufH, nbh, a2a, ah, al, nullptr);
    gemm_mma<<<ggrid, 256, SMEM_BYTES>>>(ah, al, wbh, wbl, b1, bufH, nbh, 256, 4 * WCH);
    attn_kernel<<<attn_grid, 256>>>(bufH, nbh, a2a, ah, al, nullptr);
    gemm_mma<<<ggrid, 256, SMEM_BYTES>>>(ah, al, wbh, wbl, b2, bufH, nbh, 256, 12 * WCH);
    attn_kernel<<<attn_grid, 256>>>(bufH, nbh, a2a, nullptr, nullptr, node_repr);

    readout_kernel<<<N_GRAPHS, 256>>>(node_repr, Wo1, bo1, Wo2, bo2, graph_repr, y);
}

// round 7
// speedup vs baseline: 1.9450x; 1.0232x over previous
#include <cuda_runtime.h>
#include <cuda_bf16.h>
#include <math.h>
#include <stdint.h>

#define N_NODES   50001
#define N_PAD     (N_NODES + 128)
#define N_NBRS    12
#define N_GRAPHS  1000
#define NEG_BIG   (-9000000000000000.0f)
#define HD        256

// ---------------------------------------------------------------------------
// Scratch
// ---------------------------------------------------------------------------
__device__ float g_bufH[(size_t)N_NODES * HD];                  // GEMM out (fp32)
__device__ unsigned short g_nbh[(size_t)N_PAD * HD];            // GEMM out (bf16 hi) for gather
__device__ unsigned short g_ah[(size_t)N_PAD * HD];             // next-layer A hi (bf16)
__device__ unsigned short g_al[(size_t)N_PAD * HD];             // next-layer A lo (bf16)

// Weights, layout per layer: [chunk32][n=256][k=32] bf16 hi/lo
#define WCH 8192                          // 256*32
#define WT_TOTAL (20 * WCH)
__device__ unsigned short g_wbh[WT_TOTAL];
__device__ unsigned short g_wbl[WT_TOTAL];

// ---------------------------------------------------------------------------
// helpers
// ---------------------------------------------------------------------------
__device__ __forceinline__ unsigned short f2bf(float v) {
    return __bfloat16_as_ushort(__float2bfloat16_rn(v));
}
__device__ __forceinline__ float bf2f(unsigned short u) {
    return __bfloat162float(__ushort_as_bfloat16(u));
}
__device__ __forceinline__ uint32_t pack2(unsigned short a, unsigned short b) {
    return (uint32_t)a | ((uint32_t)b << 16);
}
__device__ __forceinline__ float2 bf2x2(uint32_t u) {
    float2 r;
    r.x = __uint_as_float(u << 16);
    r.y = __uint_as_float(u & 0xffff0000u);
    return r;
}

__device__ __forceinline__ void mma_bf16(float* d, const uint32_t* a, const uint32_t* b) {
    asm volatile(
        "mma.sync.aligned.m16n8k16.row.col.f32.bf16.bf16.f32 "
        "{%0,%1,%2,%3}, {%4,%5,%6,%7}, {%8,%9}, {%0,%1,%2,%3};"
        : "+f"(d[0]), "+f"(d[1]), "+f"(d[2]), "+f"(d[3])
        : "r"(a[0]), "r"(a[1]), "r"(a[2]), "r"(a[3]), "r"(b[0]), "r"(b[1]));
}
#define LDMX4(r, addr) \
    asm volatile("ldmatrix.sync.aligned.m8n8.x4.shared.b16 {%0,%1,%2,%3}, [%4];" \
        : "=r"((r)[0]), "=r"((r)[1]), "=r"((r)[2]), "=r"((r)[3]) : "r"(addr))
#define CP16(dst, src) \
    asm volatile("cp.async.cg.shared.global [%0], [%1], 16;" :: "r"(dst), "l"(src) : "memory")
#define CPCOMMIT() asm volatile("cp.async.commit_group;" ::: "memory")
#define CPWAIT1()  asm volatile("cp.async.wait_group 1;" ::: "memory")
#define CPWAIT0()  asm volatile("cp.async.wait_group 0;" ::: "memory")

// ---------------------------------------------------------------------------
// Weight prep
// ---------------------------------------------------------------------------
__global__ void prep_w(const float* __restrict__ W0, const float* __restrict__ W1,
                       const float* __restrict__ W2,
                       unsigned short* __restrict__ bh, unsigned short* __restrict__ bl)
{
    int idx = blockIdx.x * blockDim.x + threadIdx.x;
    if (idx >= WT_TOTAL) return;
    const float* W; int K, base;
    if (idx < 4 * WCH)       { W = W0; K = 128; base = 0; }
    else if (idx < 12 * WCH) { W = W1; K = 256; base = 4 * WCH; }
    else                     { W = W2; K = 256; base = 12 * WCH; }
    int e = idx - base;
    int chunk = e >> 13;
    int rem   = e & 8191;
    int n  = rem >> 5;
    int kk = rem & 31;
    int h = n >> 5, o = n & 31;
    int k = chunk * 32 + kk;
    float v = W[((size_t)h * K + k) * 32 + o];
    unsigned short hi = f2bf(v);
    bh[idx] = hi;
    bl[idx] = f2bf(v - bf2f(hi));
}

// ---------------------------------------------------------------------------
// split_x
// ---------------------------------------------------------------------------
__global__ void split_x(const float* __restrict__ x,
                        unsigned short* __restrict__ ah, unsigned short* __restrict__ al)
{
    int i = blockIdx.x * blockDim.x + threadIdx.x;
    if (i * 4 >= N_NODES * 128) return;
    float4 v = *(const float4*)(x + i * 4);
    unsigned short hx = f2bf(v.x), hy = f2bf(v.y), hz = f2bf(v.z), hw = f2bf(v.w);
    uint2 hp, lp;
    hp.x = pack2(hx, hy); hp.y = pack2(hz, hw);
    lp.x = pack2(f2bf(v.x - bf2f(hx)), f2bf(v.y - bf2f(hy)));
    lp.y = pack2(f2bf(v.z - bf2f(hz)), f2bf(v.w - bf2f(hw)));
    *(uint2*)(ah + i * 4) = hp;
    *(uint2*)(al + i * 4) = lp;
}

// ---------------------------------------------------------------------------
// GEMM (unchanged from R6 winner)
// ---------------------------------------------------------------------------
#define SROW 80
#define SARR 10240
#define SMEM_BYTES (8 * SARR)

__global__ __launch_bounds__(256, 2)
void gemm_mma(const unsigned short* __restrict__ Ah, const unsigned short* __restrict__ Al,
              const unsigned short* __restrict__ wbh, const unsigned short* __restrict__ wbl,
              const float* __restrict__ bias, float* __restrict__ C,
              unsigned short* __restrict__ NBH, int K, int wbase)
{
    extern __shared__ char smem[];
    const uint32_t sbase = (uint32_t)__cvta_generic_to_shared(smem);

    const int tid  = threadIdx.x;
    const int wid  = tid >> 5;
    const int lane = tid & 31;
    const int g    = lane >> 2;
    const int t4   = lane & 3;
    const int wm   = wid & 1;
    const int wn   = wid >> 1;
    const int row0 = blockIdx.x * 128;
    const int col0 = blockIdx.y * 128;
    const int nch  = K >> 5;

    const int r_a  = tid >> 2, seg_a = tid & 3;

    const uint32_t aro = ((((lane >> 3) & 1) * 8 + (lane & 7)) * SROW) + ((lane >> 4) * 16);
    const uint32_t bro = ((((lane >> 4) & 1) * 8 + (lane & 7)) * SROW) + (((lane >> 3) & 1) * 16);

    auto fill = [&](int s, int c) {
        uint32_t stA = sbase + (s * 4) * SARR;
        uint32_t stB = sbase + (s * 4 + 2) * SARR;
        const unsigned short* srcB  = wbh + wbase + c * WCH + (col0 << 5);
        const unsigned short* srcBl = wbl + wbase + c * WCH + (col0 << 5);
#pragma unroll
        for (int i = 0; i < 2; i++) {
            int row = r_a + i * 64, seg = seg_a;
            size_t aoff = (size_t)(row0 + row) * K + c * 32 + seg * 8;
            uint32_t d = stA + row * SROW + seg * 16;
            CP16(d,        Ah + aoff);
            CP16(d + SARR, Al + aoff);
            size_t boff = (size_t)row * 32 + seg * 8;
            uint32_t db = stB + row * SROW + seg * 16;
            CP16(db,        srcB  + boff);
            CP16(db + SARR, srcBl + boff);
        }
    };

    float acc[4][4][4];
#pragma unroll
    for (int i = 0; i < 4; i++)
#pragma unroll
        for (int j = 0; j < 4; j++)
#pragma unroll
            for (int q = 0; q < 4; q++) acc[i][j][q] = 0.0f;

    fill(0, 0);
    CPCOMMIT();

    for (int c = 0; c < nch; c++) {
        int s = c & 1;
        if (c + 1 < nch) { fill(s ^ 1, c + 1); CPCOMMIT(); CPWAIT1(); }
        else             { CPWAIT0(); }
        __syncthreads();

        uint32_t stAh = sbase + (s * 4) * SARR + (wm * 64) * SROW + aro;
        uint32_t stAl = stAh + SARR;
        uint32_t stBh = sbase + (s * 4 + 2) * SARR + (wn * 32) * SROW + bro;
        uint32_t stBl = stBh + SARR;

#pragma unroll
        for (int k16 = 0; k16 < 2; k16++) {
            uint32_t ko = k16 * 32;
            uint32_t ah[4][4], al[4][4], bh4[2][4], bl4[2][4];
#pragma unroll
            for (int ma = 0; ma < 4; ma++) {
                LDMX4(ah[ma], stAh + ma * 16 * SROW + ko);
                LDMX4(al[ma], stAl + ma * 16 * SROW + ko);
            }
#pragma unroll
            for (int np = 0; np < 2; np++) {
                LDMX4(bh4[np], stBh + np * 16 * SROW + ko);
                LDMX4(bl4[np], stBl + np * 16 * SROW + ko);
            }
#pragma unroll
            for (int na = 0; na < 4; na++) {
                uint32_t bhf[2] = { bh4[na >> 1][(na & 1) * 2], bh4[na >> 1][(na & 1) * 2 + 1] };
                uint32_t blf[2] = { bl4[na >> 1][(na & 1) * 2], bl4[na >> 1][(na & 1) * 2 + 1] };
#pragma unroll
                for (int ma = 0; ma < 4; ma++) {
                    mma_bf16(acc[ma][na], ah[ma], bhf);
                    mma_bf16(acc[ma][na], ah[ma], blf);
                    mma_bf16(acc[ma][na], al[ma], bhf);
                }
            }
        }
        __syncthreads();
    }

#pragma unroll
    for (int ma = 0; ma < 4; ma++) {
#pragma unroll
        for (int na = 0; na < 4; na++) {
            int cg = col0 + wn * 32 + na * 8 + t4 * 2;
            float bx = __ldg(&bias[cg]);
            float by = __ldg(&bias[cg + 1]);
            int r1 = row0 + wm * 64 + ma * 16 + g;
            int r2 = r1 + 8;
            if (r1 < N_NODES) {
                float2 v = make_float2(acc[ma][na][0] + bx, acc[ma][na][1] + by);
                if (r1 == 0) v = make_float2(NEG_BIG, NEG_BIG);
                *(float2*)(C + (size_t)r1 * HD + cg) = v;
                *(uint32_t*)(NBH + (size_t)r1 * HD + cg) = pack2(f2bf(v.x), f2bf(v.y));
            }
            if (r2 < N_NODES) {
                float2 v = make_float2(acc[ma][na][2] + bx, acc[ma][na][3] + by);
                *(float2*)(C + (size_t)r2 * HD + cg) = v;
                *(uint32_t*)(NBH + (size_t)r2 * HD + cg) = pack2(f2bf(v.x), f2bf(v.y));
            }
        }
    }
}

// ---------------------------------------------------------------------------
// Attention: own fp32, neighbor bf16. Simplified softmax:
//   attn0 = 1 / (1 + sum_k exp(d_k - s0))   (exact identity; inf-safe)
// __expf / __fdividef (MUFU) + vectorized a2a loads.
// ---------------------------------------------------------------------------
__global__ __launch_bounds__(256)
void attn_kernel(const float* __restrict__ H, const unsigned short* __restrict__ NBH,
                 const int* __restrict__ a2a32,
                 unsigned short* __restrict__ outh, unsigned short* __restrict__ outl,
                 float* __restrict__ outf)
{
    const int gwarp = (blockIdx.x * blockDim.x + threadIdx.x) >> 5;
    if (gwarp >= N_NODES) return;
    const int node = gwarp;
    const int lane = threadIdx.x & 31;
    const int head = lane >> 2;
    const int part = lane & 3;

    const bool idx64 = ((a2a32[1] | a2a32[3] | a2a32[5] | a2a32[7]) == 0);

    // neighbor indices, vectorized when int32
    int nbr[N_NBRS];
    if (!idx64) {
        const int4* p = (const int4*)(a2a32 + node * N_NBRS);
        int4 q0 = p[0], q1 = p[1], q2 = p[2];
        nbr[0] = q0.x; nbr[1] = q0.y; nbr[2]  = q0.z; nbr[3]  = q0.w;
        nbr[4] = q1.x; nbr[5] = q1.y; nbr[6]  = q1.z; nbr[7]  = q1.w;
        nbr[8] = q2.x; nbr[9] = q2.y; nbr[10] = q2.z; nbr[11] = q2.w;
    } else {
#pragma unroll
        for (int k = 0; k < N_NBRS; k++) nbr[k] = a2a32[2 * (node * N_NBRS + k)];
    }

    const int off = head * 32 + part * 8;
    const float* hrow = H + (size_t)node * HD + off;
    float4 u0 = *(const float4*)hrow;
    float4 u1 = *(const float4*)(hrow + 4);
    float hn[8] = {u0.x, u0.y, u0.z, u0.w, u1.x, u1.y, u1.z, u1.w};

    float s = 0.f;
#pragma unroll
    for (int i = 0; i < 8; i++) s = fmaf(hn[i], hn[i], s);
    s += __shfl_xor_sync(0xffffffffu, s, 1);
    s += __shfl_xor_sync(0xffffffffu, s, 2);
    const float s0 = s;

    float d[N_NBRS];
#pragma unroll
    for (int k = 0; k < N_NBRS; k++) {
        uint4 p = *(const uint4*)(NBH + (size_t)nbr[k] * HD + off);
        float2 f0 = bf2x2(p.x), f1 = bf2x2(p.y), f2c = bf2x2(p.z), f3 = bf2x2(p.w);
        float dd = hn[0] * f0.x;
        dd = fmaf(hn[1], f0.y, dd);
        dd = fmaf(hn[2], f1.x, dd);
        dd = fmaf(hn[3], f1.y, dd);
        dd = fmaf(hn[4], f2c.x, dd);
        dd = fmaf(hn[5], f2c.y, dd);
        dd = fmaf(hn[6], f3.x, dd);
        dd = fmaf(hn[7], f3.y, dd);
        dd += __shfl_xor_sync(0xffffffffu, dd, 1);
        dd += __shfl_xor_sync(0xffffffffu, dd, 2);
        d[k] = dd;
    }

    float denom = 1.0f;
#pragma unroll
    for (int k = 0; k < N_NBRS; k++) denom += __expf(d[k] - s0);

    float attn0 = __fdividef(1.0f, denom);
    if (node == 0) attn0 = 0.0f;

    float v[8];
#pragma unroll
    for (int i = 0; i < 8; i++) v[i] = hn[i] * attn0;

    if (outf) {
        float* orow = outf + (size_t)node * HD + off;
        *(float4*)orow       = make_float4(v[0], v[1], v[2], v[3]);
        *(float4*)(orow + 4) = make_float4(v[4], v[5], v[6], v[7]);
    } else {
        unsigned short hh[8];
        uint4 hp, lp;
#pragma unroll
        for (int i = 0; i < 8; i++) hh[i] = f2bf(v[i]);
        hp.x = pack2(hh[0], hh[1]); hp.y = pack2(hh[2], hh[3]);
        hp.z = pack2(hh[4], hh[5]); hp.w = pack2(hh[6], hh[7]);
        lp.x = pack2(f2bf(v[0] - bf2f(hh[0])), f2bf(v[1] - bf2f(hh[1])));
        lp.y = pack2(f2bf(v[2] - bf2f(hh[2])), f2bf(v[3] - bf2f(hh[3])));
        lp.z = pack2(f2bf(v[4] - bf2f(hh[4])), f2bf(v[5] - bf2f(hh[5])));
        lp.w = pack2(f2bf(v[6] - bf2f(hh[6])), f2bf(v[7] - bf2f(hh[7])));
        *(uint4*)(outh + (size_t)node * HD + off) = hp;
        *(uint4*)(outl + (size_t)node * HD + off) = lp;
    }
}

// ---------------------------------------------------------------------------
// Readout
// ---------------------------------------------------------------------------
__global__ __launch_bounds__(256)
void readout_kernel(const float* __restrict__ node_repr,
                    const float* __restrict__ Wo1, const float* __restrict__ bo1,
                    const float* __restrict__ Wo2, const float* __restrict__ bo2,
                    float* __restrict__ graph_repr, float* __restrict__ y)
{
    __shared__ float g[HD];
    const int gi = blockIdx.x;
    const int c  = threadIdx.x;

    float ssum = 0.f;
    const float* base = node_repr + (size_t)(1 + gi * 50) * HD + c;
#pragma unroll 10
    for (int r = 0; r < 50; r++) ssum += base[(size_t)r * HD];
    g[c] = ssum;
    graph_repr[(size_t)gi * HD + c] = ssum;
    __syncthreads();

    if (c < 32) {
        float acc = bo1[c];
#pragma unroll 8
        for (int d = 0; d < HD; d++) acc = fmaf(g[d], Wo1[d * 32 + c], acc);
        acc = fmaxf(acc, 0.0f);
        float val = acc * Wo2[c];
#pragma unroll
        for (int o = 16; o > 0; o >>= 1)
            val += __shfl_xor_sync(0xffffffffu, val, o);
        if (c == 0) y[gi] = val + bo2[0];
    }
}

// ---------------------------------------------------------------------------
extern "C" void kernel_launch(void* const* d_in, const int* in_sizes, int n_in,
                              void* d_out, int out_size)
{
    const float* x   = (const float*)d_in[0];
    const int*   a2a = (const int*)d_in[1];
    const float* W0  = (const float*)d_in[3];
    const float* b0  = (const float*)d_in[4];
    const float* W1  = (const float*)d_in[5];
    const float* b1  = (const float*)d_in[6];
    const float* W2  = (const float*)d_in[7];
    const float* b2  = (const float*)d_in[8];
    const float* Wo1 = (const float*)d_in[9];
    const float* bo1 = (const float*)d_in[10];
    const float* Wo2 = (const float*)d_in[11];
    const float* bo2 = (const float*)d_in[12];

    float* out        = (float*)d_out;
    float* node_repr  = out;
    float* graph_repr = out + (size_t)N_NODES * HD;
    float* y          = graph_repr + (size_t)N_GRAPHS * HD;

    float* bufH = nullptr;
    unsigned short *nbh = nullptr, *ah = nullptr, *al = nullptr, *wbh = nullptr, *wbl = nullptr;
    cudaGetSymbolAddress((void**)&bufH, g_bufH);
    cudaGetSymbolAddress((void**)&nbh, g_nbh);
    cudaGetSymbolAddress((void**)&ah, g_ah);
    cudaGetSymbolAddress((void**)&al, g_al);
    cudaGetSymbolAddress((void**)&wbh, g_wbh);
    cudaGetSymbolAddress((void**)&wbl, g_wbl);

    cudaFuncSetAttribute(gemm_mma, cudaFuncAttributeMaxDynamicSharedMemorySize, SMEM_BYTES);

    dim3 ggrid((N_NODES + 127) / 128, 2);
    const int attn_grid = (N_NODES + 7) / 8;

    prep_w<<<(WT_TOTAL + 255) / 256, 256>>>(W0, W1, W2, wbh, wbl);
    split_x<<<(N_NODES * 128 / 4 + 255) / 256, 256>>>(x, ah, al);

    gemm_mma<<<ggrid, 256, SMEM_BYTES>>>(ah, al, wbh, wbl, b0, bufH, nbh, 128, 0);
    attn_kernel<<<attn_grid, 256>>>(bufH, nbh, a2a, ah, al, nullptr);
    gemm_mma<<<ggrid, 256, SMEM_BYTES>>>(ah, al, wbh, wbl, b1, bufH, nbh, 256, 4 * WCH);
    attn_kernel<<<attn_grid, 256>>>(bufH, nbh, a2a, ah, al, nullptr);
    gemm_mma<<<ggrid, 256, SMEM_BYTES>>>(ah, al, wbh, wbl, b2, bufH, nbh, 256, 12 * WCH);
    attn_kernel<<<attn_grid, 256>>>(bufH, nbh, a2a, nullptr, nullptr, node_repr);

    readout_kernel<<<N_GRAPHS, 256>>>(node_repr, Wo1, bo1, Wo2, bo2, graph_repr, y);
}

// round 8
// speedup vs baseline: 1.9452x; 1.0001x over previous
#include <cuda_runtime.h>
#include <cuda_bf16.h>
#include <math.h>
#include <stdint.h>

#define N_NODES   50001
#define N_PAD     (N_NODES + 128)
#define N_NBRS    12
#define N_GRAPHS  1000
#define NEG_BIG   (-9000000000000000.0f)
#define HD        256

// ---------------------------------------------------------------------------
// Scratch
// ---------------------------------------------------------------------------
__device__ float g_bufH[(size_t)N_NODES * HD];                  // GEMM out (fp32)
__device__ unsigned short g_nbh[(size_t)N_PAD * HD];            // GEMM out (bf16 hi) for gather
__device__ unsigned short g_ah[(size_t)N_PAD * HD];             // next-layer A hi (bf16)
__device__ unsigned short g_al[(size_t)N_PAD * HD];             // next-layer A lo (bf16)

#define WCH 8192                          // 256*32
#define WT_TOTAL (20 * WCH)
__device__ unsigned short g_wbh[WT_TOTAL];
__device__ unsigned short g_wbl[WT_TOTAL];

// ---------------------------------------------------------------------------
// helpers
// ---------------------------------------------------------------------------
__device__ __forceinline__ unsigned short f2bf(float v) {
    return __bfloat16_as_ushort(__float2bfloat16_rn(v));
}
__device__ __forceinline__ float bf2f(unsigned short u) {
    return __bfloat162float(__ushort_as_bfloat16(u));
}
__device__ __forceinline__ uint32_t pack2(unsigned short a, unsigned short b) {
    return (uint32_t)a | ((uint32_t)b << 16);
}

__device__ __forceinline__ void mma_bf16(float* d, const uint32_t* a, const uint32_t* b) {
    asm volatile(
        "mma.sync.aligned.m16n8k16.row.col.f32.bf16.bf16.f32 "
        "{%0,%1,%2,%3}, {%4,%5,%6,%7}, {%8,%9}, {%0,%1,%2,%3};"
        : "+f"(d[0]), "+f"(d[1]), "+f"(d[2]), "+f"(d[3])
        : "r"(a[0]), "r"(a[1]), "r"(a[2]), "r"(a[3]), "r"(b[0]), "r"(b[1]));
}
#define LDMX4(r, addr) \
    asm volatile("ldmatrix.sync.aligned.m8n8.x4.shared.b16 {%0,%1,%2,%3}, [%4];" \
        : "=r"((r)[0]), "=r"((r)[1]), "=r"((r)[2]), "=r"((r)[3]) : "r"(addr))
#define CP16(dst, src) \
    asm volatile("cp.async.cg.shared.global [%0], [%1], 16;" :: "r"(dst), "l"(src) : "memory")
#define CPCOMMIT() asm volatile("cp.async.commit_group;" ::: "memory")
#define CPWAIT1()  asm volatile("cp.async.wait_group 1;" ::: "memory")
#define CPWAIT0()  asm volatile("cp.async.wait_group 0;" ::: "memory")

// ---------------------------------------------------------------------------
// Weight prep
// ---------------------------------------------------------------------------
__global__ void prep_w(const float* __restrict__ W0, const float* __restrict__ W1,
                       const float* __restrict__ W2,
                       unsigned short* __restrict__ bh, unsigned short* __restrict__ bl)
{
    int idx = blockIdx.x * blockDim.x + threadIdx.x;
    if (idx >= WT_TOTAL) return;
    const float* W; int K, base;
    if (idx < 4 * WCH)       { W = W0; K = 128; base = 0; }
    else if (idx < 12 * WCH) { W = W1; K = 256; base = 4 * WCH; }
    else                     { W = W2; K = 256; base = 12 * WCH; }
    int e = idx - base;
    int chunk = e >> 13;
    int rem   = e & 8191;
    int n  = rem >> 5;
    int kk = rem & 31;
    int h = n >> 5, o = n & 31;
    int k = chunk * 32 + kk;
    float v = W[((size_t)h * K + k) * 32 + o];
    unsigned short hi = f2bf(v);
    bh[idx] = hi;
    bl[idx] = f2bf(v - bf2f(hi));
}

// ---------------------------------------------------------------------------
// split_x
// ---------------------------------------------------------------------------
__global__ void split_x(const float* __restrict__ x,
                        unsigned short* __restrict__ ah, unsigned short* __restrict__ al)
{
    int i = blockIdx.x * blockDim.x + threadIdx.x;
    if (i * 4 >= N_NODES * 128) return;
    float4 v = *(const float4*)(x + i * 4);
    unsigned short hx = f2bf(v.x), hy = f2bf(v.y), hz = f2bf(v.z), hw = f2bf(v.w);
    uint2 hp, lp;
    hp.x = pack2(hx, hy); hp.y = pack2(hz, hw);
    lp.x = pack2(f2bf(v.x - bf2f(hx)), f2bf(v.y - bf2f(hy)));
    lp.y = pack2(f2bf(v.z - bf2f(hz)), f2bf(v.w - bf2f(hw)));
    *(uint2*)(ah + i * 4) = hp;
    *(uint2*)(al + i * 4) = lp;
}

// ---------------------------------------------------------------------------
// GEMM (unchanged from R6/R7 winner)
// ---------------------------------------------------------------------------
#define SROW 80
#define SARR 10240
#define SMEM_BYTES (8 * SARR)

__global__ __launch_bounds__(256, 2)
void gemm_mma(const unsigned short* __restrict__ Ah, const unsigned short* __restrict__ Al,
              const unsigned short* __restrict__ wbh, const unsigned short* __restrict__ wbl,
              const float* __restrict__ bias, float* __restrict__ C,
              unsigned short* __restrict__ NBH, int K, int wbase)
{
    extern __shared__ char smem[];
    const uint32_t sbase = (uint32_t)__cvta_generic_to_shared(smem);

    const int tid  = threadIdx.x;
    const int wid  = tid >> 5;
    const int lane = tid & 31;
    const int g    = lane >> 2;
    const int t4   = lane & 3;
    const int wm   = wid & 1;
    const int wn   = wid >> 1;
    const int row0 = blockIdx.x * 128;
    const int col0 = blockIdx.y * 128;
    const int nch  = K >> 5;

    const int r_a  = tid >> 2, seg_a = tid & 3;

    const uint32_t aro = ((((lane >> 3) & 1) * 8 + (lane & 7)) * SROW) + ((lane >> 4) * 16);
    const uint32_t bro = ((((lane >> 4) & 1) * 8 + (lane & 7)) * SROW) + (((lane >> 3) & 1) * 16);

    auto fill = [&](int s, int c) {
        uint32_t stA = sbase + (s * 4) * SARR;
        uint32_t stB = sbase + (s * 4 + 2) * SARR;
        const unsigned short* srcB  = wbh + wbase + c * WCH + (col0 << 5);
        const unsigned short* srcBl = wbl + wbase + c * WCH + (col0 << 5);
#pragma unroll
        for (int i = 0; i < 2; i++) {
            int row = r_a + i * 64, seg = seg_a;
            size_t aoff = (size_t)(row0 + row) * K + c * 32 + seg * 8;
            uint32_t d = stA + row * SROW + seg * 16;
            CP16(d,        Ah + aoff);
            CP16(d + SARR, Al + aoff);
            size_t boff = (size_t)row * 32 + seg * 8;
            uint32_t db = stB + row * SROW + seg * 16;
            CP16(db,        srcB  + boff);
            CP16(db + SARR, srcBl + boff);
        }
    };

    float acc[4][4][4];
#pragma unroll
    for (int i = 0; i < 4; i++)
#pragma unroll
        for (int j = 0; j < 4; j++)
#pragma unroll
            for (int q = 0; q < 4; q++) acc[i][j][q] = 0.0f;

    fill(0, 0);
    CPCOMMIT();

    for (int c = 0; c < nch; c++) {
        int s = c & 1;
        if (c + 1 < nch) { fill(s ^ 1, c + 1); CPCOMMIT(); CPWAIT1(); }
        else             { CPWAIT0(); }
        __syncthreads();

        uint32_t stAh = sbase + (s * 4) * SARR + (wm * 64) * SROW + aro;
        uint32_t stAl = stAh + SARR;
        uint32_t stBh = sbase + (s * 4 + 2) * SARR + (wn * 32) * SROW + bro;
        uint32_t stBl = stBh + SARR;

#pragma unroll
        for (int k16 = 0; k16 < 2; k16++) {
            uint32_t ko = k16 * 32;
            uint32_t ah[4][4], al[4][4], bh4[2][4], bl4[2][4];
#pragma unroll
            for (int ma = 0; ma < 4; ma++) {
                LDMX4(ah[ma], stAh + ma * 16 * SROW + ko);
                LDMX4(al[ma], stAl + ma * 16 * SROW + ko);
            }
#pragma unroll
            for (int np = 0; np < 2; np++) {
                LDMX4(bh4[np], stBh + np * 16 * SROW + ko);
                LDMX4(bl4[np], stBl + np * 16 * SROW + ko);
            }
#pragma unroll
            for (int na = 0; na < 4; na++) {
                uint32_t bhf[2] = { bh4[na >> 1][(na & 1) * 2], bh4[na >> 1][(na & 1) * 2 + 1] };
                uint32_t blf[2] = { bl4[na >> 1][(na & 1) * 2], bl4[na >> 1][(na & 1) * 2 + 1] };
#pragma unroll
                for (int ma = 0; ma < 4; ma++) {
                    mma_bf16(acc[ma][na], ah[ma], bhf);
                    mma_bf16(acc[ma][na], ah[ma], blf);
                    mma_bf16(acc[ma][na], al[ma], bhf);
                }
            }
        }
        __syncthreads();
    }

#pragma unroll
    for (int ma = 0; ma < 4; ma++) {
#pragma unroll
        for (int na = 0; na < 4; na++) {
            int cg = col0 + wn * 32 + na * 8 + t4 * 2;
            float bx = __ldg(&bias[cg]);
            float by = __ldg(&bias[cg + 1]);
            int r1 = row0 + wm * 64 + ma * 16 + g;
            int r2 = r1 + 8;
            if (r1 < N_NODES) {
                float2 v = make_float2(acc[ma][na][0] + bx, acc[ma][na][1] + by);
                if (r1 == 0) v = make_float2(NEG_BIG, NEG_BIG);
                *(float2*)(C + (size_t)r1 * HD + cg) = v;
                *(uint32_t*)(NBH + (size_t)r1 * HD + cg) = pack2(f2bf(v.x), f2bf(v.y));
            }
            if (r2 < N_NODES) {
                float2 v = make_float2(acc[ma][na][2] + bx, acc[ma][na][3] + by);
                *(float2*)(C + (size_t)r2 * HD + cg) = v;
                *(uint32_t*)(NBH + (size_t)r2 * HD + cg) = pack2(f2bf(v.x), f2bf(v.y));
            }
        }
    }
}

// ---------------------------------------------------------------------------
// Attention: 32-bit gather offsets, batched 6+6 LDG.128 for MLP,
// softmax attn0 = 1/(1+sum exp(d_k - s0)).
// ---------------------------------------------------------------------------
__global__ __launch_bounds__(256)
void attn_kernel(const float* __restrict__ H, const unsigned short* __restrict__ NBH,
                 const int* __restrict__ a2a32,
                 unsigned short* __restrict__ outh, unsigned short* __restrict__ outl,
                 float* __restrict__ outf)
{
    const int gwarp = (blockIdx.x * blockDim.x + threadIdx.x) >> 5;
    if (gwarp >= N_NODES) return;
    const int node = gwarp;
    const int lane = threadIdx.x & 31;
    const int head = lane >> 2;
    const int part = lane & 3;

    const bool idx64 = ((a2a32[1] | a2a32[3] | a2a32[5] | a2a32[7]) == 0);

    const int off = head * 32 + part * 8;            // element offset within row
    const uint32_t offb = (uint32_t)off * 2;         // byte offset within bf16 row

    // 32-bit byte offsets into NBH: nbr*512 + offb  (max ~25.6M, fits easily)
    uint32_t nofs[N_NBRS];
    if (!idx64) {
        const int4* p = (const int4*)(a2a32 + node * N_NBRS);
        int4 q0 = p[0], q1 = p[1], q2 = p[2];
        nofs[0] = ((uint32_t)q0.x << 9) + offb; nofs[1]  = ((uint32_t)q0.y << 9) + offb;
        nofs[2] = ((uint32_t)q0.z << 9) + offb; nofs[3]  = ((uint32_t)q0.w << 9) + offb;
        nofs[4] = ((uint32_t)q1.x << 9) + offb; nofs[5]  = ((uint32_t)q1.y << 9) + offb;
        nofs[6] = ((uint32_t)q1.z << 9) + offb; nofs[7]  = ((uint32_t)q1.w << 9) + offb;
        nofs[8] = ((uint32_t)q2.x << 9) + offb; nofs[9]  = ((uint32_t)q2.y << 9) + offb;
        nofs[10] = ((uint32_t)q2.z << 9) + offb; nofs[11] = ((uint32_t)q2.w << 9) + offb;
    } else {
#pragma unroll
        for (int k = 0; k < N_NBRS; k++)
            nofs[k] = ((uint32_t)a2a32[2 * (node * N_NBRS + k)] << 9) + offb;
    }
    const char* nb = (const char*)NBH;

    const float* hrow = H + (size_t)node * HD + off;
    float4 u0 = *(const float4*)hrow;
    float4 u1 = *(const float4*)(hrow + 4);
    float hn[8] = {u0.x, u0.y, u0.z, u0.w, u1.x, u1.y, u1.z, u1.w};

    float s = 0.f;
#pragma unroll
    for (int i = 0; i < 8; i++) s = fmaf(hn[i], hn[i], s);
    s += __shfl_xor_sync(0xffffffffu, s, 1);
    s += __shfl_xor_sync(0xffffffffu, s, 2);
    const float s0 = s;

    float d[N_NBRS];
#pragma unroll
    for (int half = 0; half < 2; half++) {
        // batch 6 independent LDG.128s, then consume
        uint4 p[6];
#pragma unroll
        for (int j = 0; j < 6; j++)
            p[j] = *(const uint4*)(nb + nofs[half * 6 + j]);
#pragma unroll
        for (int j = 0; j < 6; j++) {
            uint32_t w0 = p[j].x, w1 = p[j].y, w2 = p[j].z, w3 = p[j].w;
            float dd;
            dd = hn[0] * __uint_as_float(w0 << 16);
            dd = fmaf(hn[1], __uint_as_float(w0 & 0xffff0000u), dd);
            dd = fmaf(hn[2], __uint_as_float(w1 << 16), dd);
            dd = fmaf(hn[3], __uint_as_float(w1 & 0xffff0000u), dd);
            dd = fmaf(hn[4], __uint_as_float(w2 << 16), dd);
            dd = fmaf(hn[5], __uint_as_float(w2 & 0xffff0000u), dd);
            dd = fmaf(hn[6], __uint_as_float(w3 << 16), dd);
            dd = fmaf(hn[7], __uint_as_float(w3 & 0xffff0000u), dd);
            dd += __shfl_xor_sync(0xffffffffu, dd, 1);
            dd += __shfl_xor_sync(0xffffffffu, dd, 2);
            d[half * 6 + j] = dd;
        }
    }

    float denom = 1.0f;
#pragma unroll
    for (int k = 0; k < N_NBRS; k++) denom += __expf(d[k] - s0);

    float attn0 = __fdividef(1.0f, denom);
    if (node == 0) attn0 = 0.0f;

    float v[8];
#pragma unroll
    for (int i = 0; i < 8; i++) v[i] = hn[i] * attn0;

    if (outf) {
        float* orow = outf + (size_t)node * HD + off;
        *(float4*)orow       = make_float4(v[0], v[1], v[2], v[3]);
        *(float4*)(orow + 4) = make_float4(v[4], v[5], v[6], v[7]);
    } else {
        unsigned short hh[8];
        uint4 hp, lp;
#pragma unroll
        for (int i = 0; i < 8; i++) hh[i] = f2bf(v[i]);
        hp.x = pack2(hh[0], hh[1]); hp.y = pack2(hh[2], hh[3]);
        hp.z = pack2(hh[4], hh[5]); hp.w = pack2(hh[6], hh[7]);
        lp.x = pack2(f2bf(v[0] - bf2f(hh[0])), f2bf(v[1] - bf2f(hh[1])));
        lp.y = pack2(f2bf(v[2] - bf2f(hh[2])), f2bf(v[3] - bf2f(hh[3])));
        lp.z = pack2(f2bf(v[4] - bf2f(hh[4])), f2bf(v[5] - bf2f(hh[5])));
        lp.w = pack2(f2bf(v[6] - bf2f(hh[6])), f2bf(v[7] - bf2f(hh[7])));
        *(uint4*)(outh + (size_t)node * HD + off) = hp;
        *(uint4*)(outl + (size_t)node * HD + off) = lp;
    }
}

// ---------------------------------------------------------------------------
// Readout
// ---------------------------------------------------------------------------
__global__ __launch_bounds__(256)
void readout_kernel(const float* __restrict__ node_repr,
                    const float* __restrict__ Wo1, const float* __restrict__ bo1,
                    const float* __restrict__ Wo2, const float* __restrict__ bo2,
                    float* __restrict__ graph_repr, float* __restrict__ y)
{
    __shared__ float g[HD];
    const int gi = blockIdx.x;
    const int c  = threadIdx.x;

    float ssum = 0.f;
    const float* base = node_repr + (size_t)(1 + gi * 50) * HD + c;
#pragma unroll 10
    for (int r = 0; r < 50; r++) ssum += base[(size_t)r * HD];
    g[c] = ssum;
    graph_repr[(size_t)gi * HD + c] = ssum;
    __syncthreads();

    if (c < 32) {
        float acc = bo1[c];
#pragma unroll 8
        for (int d = 0; d < HD; d++) acc = fmaf(g[d], Wo1[d * 32 + c], acc);
        acc = fmaxf(acc, 0.0f);
        float val = acc * Wo2[c];
#pragma unroll
        for (int o = 16; o > 0; o >>= 1)
            val += __shfl_xor_sync(0xffffffffu, val, o);
        if (c == 0) y[gi] = val + bo2[0];
    }
}

// ---------------------------------------------------------------------------
extern "C" void kernel_launch(void* const* d_in, const int* in_sizes, int n_in,
                              void* d_out, int out_size)
{
    const float* x   = (const float*)d_in[0];
    const int*   a2a = (const int*)d_in[1];
    const float* W0  = (const float*)d_in[3];
    const float* b0  = (const float*)d_in[4];
    const float* W1  = (const float*)d_in[5];
    const float* b1  = (const float*)d_in[6];
    const float* W2  = (const float*)d_in[7];
    const float* b2  = (const float*)d_in[8];
    const float* Wo1 = (const float*)d_in[9];
    const float* bo1 = (const float*)d_in[10];
    const float* Wo2 = (const float*)d_in[11];
    const float* bo2 = (const float*)d_in[12];

    float* out        = (float*)d_out;
    float* node_repr  = out;
    float* graph_repr = out + (size_t)N_NODES * HD;
    float* y          = graph_repr + (size_t)N_GRAPHS * HD;

    float* bufH = nullptr;
    unsigned short *nbh = nullptr, *ah = nullptr, *al = nullptr, *wbh = nullptr, *wbl = nullptr;
    cudaGetSymbolAddress((void**)&bufH, g_bufH);
    cudaGetSymbolAddress((void**)&nbh, g_nbh);
    cudaGetSymbolAddress((void**)&ah, g_ah);
    cudaGetSymbolAddress((void**)&al, g_al);
    cudaGetSymbolAddress((void**)&wbh, g_wbh);
    cudaGetSymbolAddress((void**)&wbl, g_wbl);

    cudaFuncSetAttribute(gemm_mma, cudaFuncAttributeMaxDynamicSharedMemorySize, SMEM_BYTES);

    dim3 ggrid((N_NODES + 127) / 128, 2);
    const int attn_grid = (N_NODES + 7) / 8;

    prep_w<<<(WT_TOTAL + 255) / 256, 256>>>(W0, W1, W2, wbh, wbl);
    split_x<<<(N_NODES * 128 / 4 + 255) / 256, 256>>>(x, ah, al);

    gemm_mma<<<ggrid, 256, SMEM_BYTES>>>(ah, al, wbh, wbl, b0, bufH, nbh, 128, 0);
    attn_kernel<<<attn_grid, 256>>>(bufH, nbh, a2a, ah, al, nullptr);
    gemm_mma<<<ggrid, 256, SMEM_BYTES>>>(ah, al, wbh, wbl, b1, bufH, nbh, 256, 4 * WCH);
    attn_kernel<<<attn_grid, 256>>>(bufH, nbh, a2a, ah, al, nullptr);
    gemm_mma<<<ggrid, 256, SMEM_BYTES>>>(ah, al, wbh, wbl, b2, bufH, nbh, 256, 12 * WCH);
    attn_kernel<<<attn_grid, 256>>>(bufH, nbh, a2a, nullptr, nullptr, node_repr);

    readout_kernel<<<N_GRAPHS, 256>>>(node_repr, Wo1, bo1, Wo2, bo2, graph_repr, y);
}